// round 2
// baseline (speedup 1.0000x reference)
#include <cuda_runtime.h>
#include <math.h>
#include <stdint.h>

#define NTT 730
#define NSS 2000
#define NHH 16
#define NRR 15
#define NSH (NSS*NHH)          // 32000
#define NTS (NTT*NSS)          // 1460000

// -------- scratch (device globals; no allocation) --------
__device__ __align__(128) float g_base1[256*NSS];
__device__ __align__(128) float g_base2[256*NSS];
__device__ __align__(128) float g_k1[NSH], g_k2[NSH], g_k23[NSH], g_k3[NSH];
__device__ __align__(128) float g_gl[NSH], g_qb[NSH], g_ge1[NSH], g_ge2[NSH];
__device__ __align__(128) float g_cw[NSH*NRR];
__device__ __align__(128) float g_vi[(size_t)NTT*NSH];
__device__ __align__(128) float g_vk[(size_t)NTT*NSH];
__device__ __align__(128) float g_vm[(size_t)NTT*NSH];
__device__ __align__(128) float g_Ps[NTS], g_Pl[NTS], g_E[NTS];
__device__ __align__(128) float g_QT[(size_t)NTT*NSH];

__device__ __forceinline__ float tanh_fast(float x) {
    float e = __expf(2.f * x);
    return 1.f - __fdividef(2.f, e + 1.f);   // err ~1e-7
}
__device__ __forceinline__ float sigmoid_f(float x) {
    return __fdividef(1.f, 1.f + __expf(-x));
}
__device__ __forceinline__ float hsig(float x) {
    return __saturatef(x * (1.f/6.f) + 0.5f);
}

// =====================================================================
// Kernel A: per-basin MLPs (w, wR) + precomputed bases for v1/v2
// =====================================================================
__global__ __launch_bounds__(256) void prep_kernel(
    const float* __restrict__ xc,
    const float* __restrict__ fc_W1,  const float* __restrict__ fc_b1,
    const float* __restrict__ fc_W2,  const float* __restrict__ fc_b2,
    const float* __restrict__ fcR_W1, const float* __restrict__ fcR_b1,
    const float* __restrict__ fcR_W2, const float* __restrict__ fcR_b2,
    const float* __restrict__ fcT1_W1,const float* __restrict__ fcT1_b1,
    const float* __restrict__ fcT2_W1,const float* __restrict__ fcT2_b1)
{
    int s = blockIdx.x;
    int tid = threadIdx.x;
    __shared__ float sxc[32];
    __shared__ float sh_h[256], sh_hR[256];
    __shared__ float sh_w[160], sh_wR[240];
    __shared__ float sh_ga[16];

    if (tid < 32) sxc[tid] = xc[s*32 + tid];
    __syncthreads();

    {   // hidden layers + bases (thread = hidden unit k)
        int k = tid;
        float a0 = fc_b1[k], a1 = fcR_b1[k], a2 = fcT1_b1[k], a3 = fcT2_b1[k];
        #pragma unroll
        for (int g = 0; g < 32; g++) {
            float xg = sxc[g];
            a0 += xg * fc_W1 [k*32 + g];
            a1 += xg * fcR_W1[k*32 + g];
            a2 += xg * fcT1_W1[k*33 + 1 + g];
            a3 += xg * fcT2_W1[k*35 + 3 + g];
        }
        sh_h[k]  = tanh_fast(a0);
        sh_hR[k] = tanh_fast(a1);
        g_base1[k*NSS + s] = a2;   // pre-tanh; LAI term added later
        g_base2[k*NSS + s] = a3;
    }
    __syncthreads();

    int warp = tid >> 5, lane = tid & 31;
    for (int o = warp; o < 400; o += 8) {
        float sum = 0.f;
        if (o < 160) {
            const float* w = fc_W2 + o*256;
            for (int k = lane; k < 256; k += 32) sum += sh_h[k] * w[k];
        } else {
            const float* w = fcR_W2 + (o-160)*256;
            for (int k = lane; k < 256; k += 32) sum += sh_hR[k] * w[k];
        }
        #pragma unroll
        for (int off = 16; off; off >>= 1) sum += __shfl_down_sync(0xffffffffu, sum, off);
        if (lane == 0) {
            if (o < 160) sh_w[o] = sum + fc_b2[o];
            else         sh_wR[o-160] = sum + fcR_b2[o-160];
        }
    }
    __syncthreads();

    if (tid < 16) {
        int h = tid, g = s*16 + h;
        g_k1 [g] = sigmoid_f(sh_w[ 16 + h]);
        g_k2 [g] = sigmoid_f(sh_w[ 32 + h]);
        g_k23[g] = sigmoid_f(sh_w[ 48 + h]);
        g_k3 [g] = sigmoid_f(sh_w[ 64 + h]) * 0.1f;
        g_gl [g] = __expf(sh_w[ 80 + h]) * 2.f;
        g_qb [g] = fmaxf(sh_w[112 + h], 0.f);
        g_ge1[g] = fmaxf(sh_w[128 + h], 0.f);
        g_ge2[g] = fmaxf(sh_w[144 + h], 0.f);
        float m = -1e30f;
        #pragma unroll
        for (int j = 0; j < 16; j++) m = fmaxf(m, sh_w[96 + j]);
        float den = 0.f;
        #pragma unroll
        for (int j = 0; j < 16; j++) den += __expf(sh_w[96 + j] - m);
        sh_ga[h] = __fdividef(__expf(sh_w[96 + h] - m), den);
    }
    __syncthreads();

    if (tid < 240) {
        int h = tid / 15, d = tid - h*15;
        g_cw[(s*16 + h)*15 + d] = sh_ga[h] * fmaxf(sh_wR[h*15 + (14 - d)], 0.f);
    }
}

// =====================================================================
// Kernel B: fused per-(t,s) MLPs with packed fma.rn.f32x2 accumulation
// block = 256 threads = 8 warps; warp = one t, lanes = 32 basins
// =====================================================================
#define TPASS 8
#define TCHUNK 32
#define SMEM_B_FLOATS (256*32*2 + 256*4 + 256*48 + 48)
#define SMEM_B_BYTES (SMEM_B_FLOATS*4)

__global__ __launch_bounds__(256) void mlp_kernel(
    const float* __restrict__ x,
    const float* __restrict__ fcT1_W1, const float* __restrict__ fcT2_W1,
    const float* __restrict__ fcT1_W2, const float* __restrict__ fcT1_b2,
    const float* __restrict__ fcT2_W2, const float* __restrict__ fcT2_b2)
{
    extern __shared__ float smem[];
    float*  sb1   = smem;                       // [256][32]
    float*  sb2   = sb1 + 256*32;               // [256][32]
    float4* swc   = (float4*)(sb2 + 256*32);    // [256] {c_LAI, c_R, c_T1, c_T2}
    float*  sw2   = (float*)(swc + 256);        // [256][48]  (k-major, 16B aligned)
    float*  sbias = sw2 + 256*48;               // [48]

    int tid = threadIdx.x;
    int s0 = blockIdx.y * 32;
    int t0 = blockIdx.x * TCHUNK;

    for (int i = tid; i < 256*32; i += 256) {
        int k = i >> 5, j = i & 31;
        int s = s0 + j;
        float v1 = 0.f, v2 = 0.f;
        if (s < NSS) { v1 = g_base1[k*NSS + s]; v2 = g_base2[k*NSS + s]; }
        sb1[i] = v1; sb2[i] = v2;
    }
    swc[tid] = make_float4(fcT1_W1[tid*33], fcT2_W1[tid*35],
                           fcT2_W1[tid*35 + 1], fcT2_W1[tid*35 + 2]);
    for (int i = tid; i < 256*48; i += 256) {
        int k = i / 48, o = i - k*48;
        sw2[i] = (o < 32) ? fcT1_W2[o*256 + k] : fcT2_W2[(o-32)*256 + k];
    }
    if (tid < 48) sbias[tid] = (tid < 32) ? fcT1_b2[tid] : fcT2_b2[tid - 32];
    __syncthreads();

    int lane = tid & 31, warp = tid >> 5;
    int s = s0 + lane;

    for (int p = 0; p < TCHUNK/TPASS; p++) {
        int t = t0 + p*TPASS + warp;
        if (t >= NTT || s >= NSS) continue;

        const float* xe = x + (size_t)(t*NSS + s)*6;
        float P = xe[0], E = xe[1], T1v = xe[2], T2v = xe[3], Rv = xe[4], LAI = xe[5];

        // snow/rain partition vp
        float denom = T2v - T1v;
        float ratio = (T1v + T2v) / (denom == 0.f ? 1.f : denom);
        ratio = fminf(fmaxf(ratio, -1.f), 1.f);
        if ((T1v >= 0.f) || (T2v <= 0.f)) ratio = 0.f;
        float vp = 1.f - acosf(ratio) / 3.1415f;
        if (T1v >= 0.f) vp = 1.f;
        if (T2v <= 0.f) vp = 0.f;
        int ts = t*NSS + s;
        g_Ps[ts] = P * (1.f - vp);
        g_Pl[ts] = P * vp;
        g_E[ts]  = E;

        // packed accumulators: pair q = outputs (2q, 2q+1), init with bias
        uint64_t acc[24];
        {
            const uint64_t* b2 = (const uint64_t*)sbias;
            #pragma unroll
            for (int q = 0; q < 24; q++) acc[q] = b2[q];
        }

        #pragma unroll 2
        for (int k = 0; k < 256; k++) {
            float4 wc = swc[k];
            float h1 = tanh_fast(fmaf(LAI, wc.x, sb1[(k<<5) + lane]));
            float h2 = tanh_fast(fmaf(Rv, wc.y, fmaf(T1v, wc.z,
                                 fmaf(T2v, wc.w, sb2[(k<<5) + lane]))));
            uint64_t hh1, hh2;
            asm("mov.b64 %0, {%1, %1};" : "=l"(hh1) : "f"(h1));
            asm("mov.b64 %0, {%1, %1};" : "=l"(hh2) : "f"(h2));
            const ulonglong2* wv = (const ulonglong2*)(sw2 + k*48);
            #pragma unroll
            for (int q = 0; q < 8; q++) {          // outputs 0..31 <- h1
                ulonglong2 w2 = wv[q];
                asm("fma.rn.f32x2 %0, %1, %2, %0;" : "+l"(acc[2*q])   : "l"(w2.x), "l"(hh1));
                asm("fma.rn.f32x2 %0, %1, %2, %0;" : "+l"(acc[2*q+1]) : "l"(w2.y), "l"(hh1));
            }
            #pragma unroll
            for (int q = 8; q < 12; q++) {         // outputs 32..47 <- h2
                ulonglong2 w2 = wv[q];
                asm("fma.rn.f32x2 %0, %1, %2, %0;" : "+l"(acc[2*q])   : "l"(w2.x), "l"(hh2));
                asm("fma.rn.f32x2 %0, %1, %2, %0;" : "+l"(acc[2*q+1]) : "l"(w2.y), "l"(hh2));
            }
        }

        float o[48];
        #pragma unroll
        for (int q = 0; q < 24; q++)
            asm("mov.b64 {%0, %1}, %2;" : "=f"(o[2*q]), "=f"(o[2*q+1]) : "l"(acc[q]));

        size_t base = (size_t)t*NSH + s*16;
        #pragma unroll
        for (int q = 0; q < 4; q++) {
            float4 a;
            a.x = hsig(o[4*q+0]); a.y = hsig(o[4*q+1]);
            a.z = hsig(o[4*q+2]); a.w = hsig(o[4*q+3]);
            *(float4*)(g_vi + base + 4*q) = a;
            float4 b;
            b.x = hsig(o[16+4*q+0]); b.y = hsig(o[16+4*q+1]);
            b.z = hsig(o[16+4*q+2]); b.w = hsig(o[16+4*q+3]);
            *(float4*)(g_vk + base + 4*q) = b;
            float4 c;
            c.x = __expf(2.f*o[32+4*q+0]); c.y = __expf(2.f*o[32+4*q+1]);
            c.z = __expf(2.f*o[32+4*q+2]); c.w = __expf(2.f*o[32+4*q+3]);
            *(float4*)(g_vm + base + 4*q) = c;
        }
    }
}

// =====================================================================
// Kernel C: sequential reservoir scan; thread = (s,h)
// =====================================================================
__global__ __launch_bounds__(128) void scan_kernel()
{
    int g = blockIdx.x * 128 + threadIdx.x;
    if (g >= NSH) return;
    int s = g >> 4;
    float k1 = g_k1[g], k2 = g_k2[g], k23 = g_k23[g], k3 = g_k3[g];
    float gl = g_gl[g], qb = g_qb[g], ge1 = g_ge1[g], ge2 = g_ge2[g];
    float S0 = 0.f, Sv = 0.f, S2 = 0.f, S3 = 0.f;

    #pragma unroll 4
    for (int t = 0; t < NTT; t++) {
        int ts = t*NSS + s;
        size_t tg = (size_t)t*NSH + g;
        float Ps = g_Ps[ts], Pl = g_Pl[ts], E = g_E[ts];
        float vi = g_vi[tg], vk = g_vk[tg], vm = g_vm[tg];

        float H0  = S0 + Ps;
        float qSm = fminf(H0, vm);
        float Hv  = fmaxf(Sv + Pl*(1.f - vi) - E*ge1, 0.f);
        float qv  = Sv * vk;
        float H2  = fmaxf(S2 + qSm + qv - E*ge2 + Pl*vi, 0.f);
        float x1  = H2 - gl;
        float Q1  = (x1 > 0.f) ? exp2f(k1 * __log2f(x1)) : 0.f;
        float q2  = fminf(H2, gl) * k2;
        float Q2  = q2 * (1.f - k23);
        float H3  = S3 + q2 * k23;
        float Q3  = H3 * k3 + qb;

        S0 = H0 - qSm;
        Sv = Hv - qv;
        S2 = H2 - Q1 - q2;
        S3 = H3 - Q3;
        g_QT[tg] = Q1 + Q2 + Q3;
    }
}

// =====================================================================
// Kernel D: causal depthwise conv + head-sum, register-blocked 4 t/thread
// block = one basin, 192 threads cover all 730 timesteps
// =====================================================================
#define CVT 192
#define CVS 788                       // row stride (floats): 16B-aligned, low conflicts
__global__ __launch_bounds__(CVT) void conv_kernel(float* __restrict__ out)
{
    __shared__ float shQ[16*CVS];     // shQ[h][j] = Q[j-14] (zero-padded)
    __shared__ float shc[NHH*NRR];
    int s = blockIdx.x;
    int tid = threadIdx.x;

    // coalesced fill: consecutive tid -> consecutive h within one timestep
    for (int i = tid; i < 16*CVS; i += CVT) {
        int j = i >> 4, h = i & 15;   // j in [0, CVS)
        int t = j - 14;
        shQ[h*CVS + j] = (t >= 0 && t < NTT)
            ? g_QT[(size_t)t*NSH + s*16 + h] : 0.f;
    }
    for (int i = tid; i < 240; i += CVT) shc[i] = g_cw[s*240 + i];
    __syncthreads();

    int tb = tid * 4;                 // this thread's 4 outputs: t = tb..tb+3
    if (tb < NTT) {
        float acc0 = 0.f, acc1 = 0.f, acc2 = 0.f, acc3 = 0.f;
        #pragma unroll
        for (int h = 0; h < 16; h++) {
            const float4* qw = (const float4*)(shQ + h*CVS + tb);
            float w[20];
            #pragma unroll
            for (int v = 0; v < 5; v++) {
                float4 q4 = qw[v];
                w[4*v+0] = q4.x; w[4*v+1] = q4.y; w[4*v+2] = q4.z; w[4*v+3] = q4.w;
            }
            #pragma unroll
            for (int d = 0; d < 15; d++) {
                float c = shc[h*15 + d];
                // out t = tb+e : Q[t-d] = shQ[h][t-d+14] = w[e+14-d]
                acc0 += w[14 - d]     * c;
                acc1 += w[15 - d]     * c;
                acc2 += w[16 - d]     * c;
                acc3 += w[17 - d]     * c;
            }
        }
        out[(tb+0)*NSS + s] = acc0;
        if (tb+1 < NTT) out[(tb+1)*NSS + s] = acc1;
        if (tb+2 < NTT) out[(tb+2)*NSS + s] = acc2;
        if (tb+3 < NTT) out[(tb+3)*NSS + s] = acc3;
    }
}

// =====================================================================
extern "C" void kernel_launch(void* const* d_in, const int* in_sizes, int n_in,
                              void* d_out, int out_size)
{
    const float* x       = (const float*)d_in[0];
    const float* xc      = (const float*)d_in[1];
    const float* fc_W1   = (const float*)d_in[2];
    const float* fc_b1   = (const float*)d_in[3];
    const float* fc_W2   = (const float*)d_in[4];
    const float* fc_b2   = (const float*)d_in[5];
    const float* fcR_W1  = (const float*)d_in[6];
    const float* fcR_b1  = (const float*)d_in[7];
    const float* fcR_W2  = (const float*)d_in[8];
    const float* fcR_b2  = (const float*)d_in[9];
    const float* fcT1_W1 = (const float*)d_in[10];
    const float* fcT1_b1 = (const float*)d_in[11];
    const float* fcT1_W2 = (const float*)d_in[12];
    const float* fcT1_b2 = (const float*)d_in[13];
    const float* fcT2_W1 = (const float*)d_in[14];
    const float* fcT2_b1 = (const float*)d_in[15];
    const float* fcT2_W2 = (const float*)d_in[16];
    const float* fcT2_b2 = (const float*)d_in[17];

    cudaFuncSetAttribute(mlp_kernel, cudaFuncAttributeMaxDynamicSharedMemorySize,
                         SMEM_B_BYTES);

    prep_kernel<<<NSS, 256>>>(xc, fc_W1, fc_b1, fc_W2, fc_b2,
                              fcR_W1, fcR_b1, fcR_W2, fcR_b2,
                              fcT1_W1, fcT1_b1, fcT2_W1, fcT2_b1);

    dim3 gB((NTT + TCHUNK - 1)/TCHUNK, (NSS + 31)/32);
    mlp_kernel<<<gB, 256, SMEM_B_BYTES>>>(x, fcT1_W1, fcT2_W1,
                                          fcT1_W2, fcT1_b2, fcT2_W2, fcT2_b2);

    scan_kernel<<<(NSH + 127)/128, 128>>>();

    conv_kernel<<<NSS, CVT>>>((float*)d_out);
}

// round 3
// speedup vs baseline: 1.4601x; 1.4601x over previous
#include <cuda_runtime.h>
#include <math.h>
#include <stdint.h>

#define NTT 730
#define NSS 2000
#define NHH 16
#define NRR 15
#define NSH (NSS*NHH)          // 32000
#define NTS (NTT*NSS)          // 1460000

// -------- scratch (device globals; no allocation) --------
__device__ __align__(128) float g_base1[256*NSS];
__device__ __align__(128) float g_base2[256*NSS];
__device__ __align__(128) float g_k1[NSH], g_k2[NSH], g_k23[NSH], g_k3[NSH];
__device__ __align__(128) float g_gl[NSH], g_qb[NSH], g_ge1[NSH], g_ge2[NSH];
__device__ __align__(128) float g_cw[NSH*NRR];
__device__ __align__(128) float g_vi[(size_t)NTT*NSH];
__device__ __align__(128) float g_vk[(size_t)NTT*NSH];
__device__ __align__(128) float g_vm[(size_t)NTT*NSH];
__device__ __align__(128) float g_Ps[NTS], g_Pl[NTS], g_E[NTS];
__device__ __align__(128) float g_QT[(size_t)NTT*NSH];

__device__ __forceinline__ float tanh_fast(float x) {
    float e = __expf(2.f * x);
    return 1.f - __fdividef(2.f, e + 1.f);   // err ~1e-7
}
__device__ __forceinline__ float sigmoid_f(float x) {
    return __fdividef(1.f, 1.f + __expf(-x));
}
__device__ __forceinline__ float hsig(float x) {
    return __saturatef(x * (1.f/6.f) + 0.5f);
}

// =====================================================================
// Kernel A: per-basin MLPs (w, wR) + precomputed bases for v1/v2
// =====================================================================
__global__ __launch_bounds__(256) void prep_kernel(
    const float* __restrict__ xc,
    const float* __restrict__ fc_W1,  const float* __restrict__ fc_b1,
    const float* __restrict__ fc_W2,  const float* __restrict__ fc_b2,
    const float* __restrict__ fcR_W1, const float* __restrict__ fcR_b1,
    const float* __restrict__ fcR_W2, const float* __restrict__ fcR_b2,
    const float* __restrict__ fcT1_W1,const float* __restrict__ fcT1_b1,
    const float* __restrict__ fcT2_W1,const float* __restrict__ fcT2_b1)
{
    int s = blockIdx.x;
    int tid = threadIdx.x;
    __shared__ float sxc[32];
    __shared__ float sh_h[256], sh_hR[256];
    __shared__ float sh_w[160], sh_wR[240];
    __shared__ float sh_ga[16];

    if (tid < 32) sxc[tid] = xc[s*32 + tid];
    __syncthreads();

    {   // hidden layers + bases (thread = hidden unit k)
        int k = tid;
        float a0 = fc_b1[k], a1 = fcR_b1[k], a2 = fcT1_b1[k], a3 = fcT2_b1[k];
        #pragma unroll
        for (int g = 0; g < 32; g++) {
            float xg = sxc[g];
            a0 += xg * fc_W1 [k*32 + g];
            a1 += xg * fcR_W1[k*32 + g];
            a2 += xg * fcT1_W1[k*33 + 1 + g];
            a3 += xg * fcT2_W1[k*35 + 3 + g];
        }
        sh_h[k]  = tanh_fast(a0);
        sh_hR[k] = tanh_fast(a1);
        g_base1[k*NSS + s] = a2;   // pre-tanh; LAI term added later
        g_base2[k*NSS + s] = a3;
    }
    __syncthreads();

    int warp = tid >> 5, lane = tid & 31;
    for (int o = warp; o < 400; o += 8) {
        float sum = 0.f;
        if (o < 160) {
            const float* w = fc_W2 + o*256;
            for (int k = lane; k < 256; k += 32) sum += sh_h[k] * w[k];
        } else {
            const float* w = fcR_W2 + (o-160)*256;
            for (int k = lane; k < 256; k += 32) sum += sh_hR[k] * w[k];
        }
        #pragma unroll
        for (int off = 16; off; off >>= 1) sum += __shfl_down_sync(0xffffffffu, sum, off);
        if (lane == 0) {
            if (o < 160) sh_w[o] = sum + fc_b2[o];
            else         sh_wR[o-160] = sum + fcR_b2[o-160];
        }
    }
    __syncthreads();

    if (tid < 16) {
        int h = tid, g = s*16 + h;
        g_k1 [g] = sigmoid_f(sh_w[ 16 + h]);
        g_k2 [g] = sigmoid_f(sh_w[ 32 + h]);
        g_k23[g] = sigmoid_f(sh_w[ 48 + h]);
        g_k3 [g] = sigmoid_f(sh_w[ 64 + h]) * 0.1f;
        g_gl [g] = __expf(sh_w[ 80 + h]) * 2.f;
        g_qb [g] = fmaxf(sh_w[112 + h], 0.f);
        g_ge1[g] = fmaxf(sh_w[128 + h], 0.f);
        g_ge2[g] = fmaxf(sh_w[144 + h], 0.f);
        float m = -1e30f;
        #pragma unroll
        for (int j = 0; j < 16; j++) m = fmaxf(m, sh_w[96 + j]);
        float den = 0.f;
        #pragma unroll
        for (int j = 0; j < 16; j++) den += __expf(sh_w[96 + j] - m);
        sh_ga[h] = __fdividef(__expf(sh_w[96 + h] - m), den);
    }
    __syncthreads();

    if (tid < 240) {
        int h = tid / 15, d = tid - h*15;
        g_cw[(s*16 + h)*15 + d] = sh_ga[h] * fmaxf(sh_wR[h*15 + (14 - d)], 0.f);
    }
}

// =====================================================================
// Kernel B: fused per-(t,s) MLPs, scalar FFMA, 2 timesteps per thread
// block = 256 threads = 8 warps; warp = 2 consecutive t, lanes = 32 basins
// =====================================================================
#define TCHUNK 32
#define SMEM_B_FLOATS (256*32*2 + 256*4 + 256*48 + 48)
#define SMEM_B_BYTES (SMEM_B_FLOATS*4)

__global__ __launch_bounds__(256) void mlp_kernel(
    const float* __restrict__ x,
    const float* __restrict__ fcT1_W1, const float* __restrict__ fcT2_W1,
    const float* __restrict__ fcT1_W2, const float* __restrict__ fcT1_b2,
    const float* __restrict__ fcT2_W2, const float* __restrict__ fcT2_b2)
{
    extern __shared__ float smem[];
    float*  sb1   = smem;                       // [256][32]
    float*  sb2   = sb1 + 256*32;               // [256][32]
    float4* swc   = (float4*)(sb2 + 256*32);    // [256] {c_LAI, c_R, c_T1, c_T2}
    float*  sw2   = (float*)(swc + 256);        // [256][48]  (k-major, 16B aligned)
    float*  sbias = sw2 + 256*48;               // [48]

    int tid = threadIdx.x;
    int s0 = blockIdx.y * 32;
    int t0 = blockIdx.x * TCHUNK;

    for (int i = tid; i < 256*32; i += 256) {
        int k = i >> 5, j = i & 31;
        int s = s0 + j;
        float v1 = 0.f, v2 = 0.f;
        if (s < NSS) { v1 = g_base1[k*NSS + s]; v2 = g_base2[k*NSS + s]; }
        sb1[i] = v1; sb2[i] = v2;
    }
    swc[tid] = make_float4(fcT1_W1[tid*33], fcT2_W1[tid*35],
                           fcT2_W1[tid*35 + 1], fcT2_W1[tid*35 + 2]);
    for (int i = tid; i < 256*48; i += 256) {
        int k = i / 48, o = i - k*48;
        sw2[i] = (o < 32) ? fcT1_W2[o*256 + k] : fcT2_W2[(o-32)*256 + k];
    }
    if (tid < 48) sbias[tid] = (tid < 32) ? fcT1_b2[tid] : fcT2_b2[tid - 32];
    __syncthreads();

    int lane = tid & 31, warp = tid >> 5;
    int s = s0 + lane;
    if (s >= NSS) return;   // no further block-wide syncs

    for (int p = 0; p < 2; p++) {
        int ta = t0 + p*16 + warp*2;       // this thread's two timesteps
        if (ta >= NTT) continue;
        int tb = ta + 1;
        bool vb = (tb < NTT);
        int tbl = vb ? tb : ta;            // clamped for loads

        const float* xa = x + (size_t)(ta *NSS + s)*6;
        const float* xb = x + (size_t)(tbl*NSS + s)*6;
        float Pa = xa[0], Ea = xa[1], T1a = xa[2], T2a = xa[3], Ra = xa[4], La = xa[5];
        float Pb = xb[0], Eb = xb[1], T1b = xb[2], T2b = xb[3], Rb = xb[4], Lb = xb[5];

        // snow/rain partition (both timesteps)
        {
            float dn = T2a - T1a;
            float r = (T1a + T2a) / (dn == 0.f ? 1.f : dn);
            r = fminf(fmaxf(r, -1.f), 1.f);
            if ((T1a >= 0.f) || (T2a <= 0.f)) r = 0.f;
            float vp = 1.f - acosf(r) / 3.1415f;
            if (T1a >= 0.f) vp = 1.f;
            if (T2a <= 0.f) vp = 0.f;
            int ts = ta*NSS + s;
            g_Ps[ts] = Pa * (1.f - vp);
            g_Pl[ts] = Pa * vp;
            g_E[ts]  = Ea;
        }
        if (vb) {
            float dn = T2b - T1b;
            float r = (T1b + T2b) / (dn == 0.f ? 1.f : dn);
            r = fminf(fmaxf(r, -1.f), 1.f);
            if ((T1b >= 0.f) || (T2b <= 0.f)) r = 0.f;
            float vp = 1.f - acosf(r) / 3.1415f;
            if (T1b >= 0.f) vp = 1.f;
            if (T2b <= 0.f) vp = 0.f;
            int ts = tb*NSS + s;
            g_Ps[ts] = Pb * (1.f - vp);
            g_Pl[ts] = Pb * vp;
            g_E[ts]  = Eb;
        }

        float accA[48], accB[48];
        #pragma unroll
        for (int o = 0; o < 48; o++) { accA[o] = 0.f; accB[o] = 0.f; }

        for (int k = 0; k < 256; k++) {
            float b1  = sb1[(k<<5) + lane];
            float b2v = sb2[(k<<5) + lane];
            float4 wc = swc[k];
            float h1a = tanh_fast(fmaf(La, wc.x, b1));
            float h1b = tanh_fast(fmaf(Lb, wc.x, b1));
            float h2a = tanh_fast(fmaf(Ra, wc.y, fmaf(T1a, wc.z, fmaf(T2a, wc.w, b2v))));
            float h2b = tanh_fast(fmaf(Rb, wc.y, fmaf(T1b, wc.z, fmaf(T2b, wc.w, b2v))));
            const float4* wv = (const float4*)(sw2 + k*48);
            #pragma unroll
            for (int q = 0; q < 8; q++) {          // outputs 0..31 <- h1
                float4 w4 = wv[q];
                accA[4*q+0] = fmaf(w4.x, h1a, accA[4*q+0]);
                accA[4*q+1] = fmaf(w4.y, h1a, accA[4*q+1]);
                accA[4*q+2] = fmaf(w4.z, h1a, accA[4*q+2]);
                accA[4*q+3] = fmaf(w4.w, h1a, accA[4*q+3]);
                accB[4*q+0] = fmaf(w4.x, h1b, accB[4*q+0]);
                accB[4*q+1] = fmaf(w4.y, h1b, accB[4*q+1]);
                accB[4*q+2] = fmaf(w4.z, h1b, accB[4*q+2]);
                accB[4*q+3] = fmaf(w4.w, h1b, accB[4*q+3]);
            }
            #pragma unroll
            for (int q = 8; q < 12; q++) {         // outputs 32..47 <- h2
                float4 w4 = wv[q];
                accA[4*q+0] = fmaf(w4.x, h2a, accA[4*q+0]);
                accA[4*q+1] = fmaf(w4.y, h2a, accA[4*q+1]);
                accA[4*q+2] = fmaf(w4.z, h2a, accA[4*q+2]);
                accA[4*q+3] = fmaf(w4.w, h2a, accA[4*q+3]);
                accB[4*q+0] = fmaf(w4.x, h2b, accB[4*q+0]);
                accB[4*q+1] = fmaf(w4.y, h2b, accB[4*q+1]);
                accB[4*q+2] = fmaf(w4.z, h2b, accB[4*q+2]);
                accB[4*q+3] = fmaf(w4.w, h2b, accB[4*q+3]);
            }
        }

        size_t baseA = (size_t)ta*NSH + s*16;
        #pragma unroll
        for (int q = 0; q < 4; q++) {
            float4 a;
            a.x = hsig(accA[4*q+0] + sbias[4*q+0]);
            a.y = hsig(accA[4*q+1] + sbias[4*q+1]);
            a.z = hsig(accA[4*q+2] + sbias[4*q+2]);
            a.w = hsig(accA[4*q+3] + sbias[4*q+3]);
            *(float4*)(g_vi + baseA + 4*q) = a;
            float4 b;
            b.x = hsig(accA[16+4*q+0] + sbias[16+4*q+0]);
            b.y = hsig(accA[16+4*q+1] + sbias[16+4*q+1]);
            b.z = hsig(accA[16+4*q+2] + sbias[16+4*q+2]);
            b.w = hsig(accA[16+4*q+3] + sbias[16+4*q+3]);
            *(float4*)(g_vk + baseA + 4*q) = b;
            float4 c;
            c.x = __expf(2.f*(accA[32+4*q+0] + sbias[32+4*q+0]));
            c.y = __expf(2.f*(accA[32+4*q+1] + sbias[32+4*q+1]));
            c.z = __expf(2.f*(accA[32+4*q+2] + sbias[32+4*q+2]));
            c.w = __expf(2.f*(accA[32+4*q+3] + sbias[32+4*q+3]));
            *(float4*)(g_vm + baseA + 4*q) = c;
        }
        if (vb) {
            size_t baseB = (size_t)tb*NSH + s*16;
            #pragma unroll
            for (int q = 0; q < 4; q++) {
                float4 a;
                a.x = hsig(accB[4*q+0] + sbias[4*q+0]);
                a.y = hsig(accB[4*q+1] + sbias[4*q+1]);
                a.z = hsig(accB[4*q+2] + sbias[4*q+2]);
                a.w = hsig(accB[4*q+3] + sbias[4*q+3]);
                *(float4*)(g_vi + baseB + 4*q) = a;
                float4 b;
                b.x = hsig(accB[16+4*q+0] + sbias[16+4*q+0]);
                b.y = hsig(accB[16+4*q+1] + sbias[16+4*q+1]);
                b.z = hsig(accB[16+4*q+2] + sbias[16+4*q+2]);
                b.w = hsig(accB[16+4*q+3] + sbias[16+4*q+3]);
                *(float4*)(g_vk + baseB + 4*q) = b;
                float4 c;
                c.x = __expf(2.f*(accB[32+4*q+0] + sbias[32+4*q+0]));
                c.y = __expf(2.f*(accB[32+4*q+1] + sbias[32+4*q+1]));
                c.z = __expf(2.f*(accB[32+4*q+2] + sbias[32+4*q+2]));
                c.w = __expf(2.f*(accB[32+4*q+3] + sbias[32+4*q+3]));
                *(float4*)(g_vm + baseB + 4*q) = c;
            }
        }
    }
}

// =====================================================================
// Kernel C: sequential reservoir scan; thread = (s,h)
// =====================================================================
__global__ __launch_bounds__(128) void scan_kernel()
{
    int g = blockIdx.x * 128 + threadIdx.x;
    if (g >= NSH) return;
    int s = g >> 4;
    float k1 = g_k1[g], k2 = g_k2[g], k23 = g_k23[g], k3 = g_k3[g];
    float gl = g_gl[g], qb = g_qb[g], ge1 = g_ge1[g], ge2 = g_ge2[g];
    float S0 = 0.f, Sv = 0.f, S2 = 0.f, S3 = 0.f;

    #pragma unroll 4
    for (int t = 0; t < NTT; t++) {
        int ts = t*NSS + s;
        size_t tg = (size_t)t*NSH + g;
        float Ps = g_Ps[ts], Pl = g_Pl[ts], E = g_E[ts];
        float vi = g_vi[tg], vk = g_vk[tg], vm = g_vm[tg];

        float H0  = S0 + Ps;
        float qSm = fminf(H0, vm);
        float Hv  = fmaxf(Sv + Pl*(1.f - vi) - E*ge1, 0.f);
        float qv  = Sv * vk;
        float H2  = fmaxf(S2 + qSm + qv - E*ge2 + Pl*vi, 0.f);
        float x1  = H2 - gl;
        float Q1  = (x1 > 0.f) ? exp2f(k1 * __log2f(x1)) : 0.f;
        float q2  = fminf(H2, gl) * k2;
        float Q2  = q2 * (1.f - k23);
        float H3  = S3 + q2 * k23;
        float Q3  = H3 * k3 + qb;

        S0 = H0 - qSm;
        Sv = Hv - qv;
        S2 = H2 - Q1 - q2;
        S3 = H3 - Q3;
        g_QT[tg] = Q1 + Q2 + Q3;
    }
}

// =====================================================================
// Kernel D: causal depthwise conv + head-sum, register-blocked 4 t/thread
// =====================================================================
#define CVT 192
#define CVS 788                       // row stride (floats): 16B-aligned, low conflicts
__global__ __launch_bounds__(CVT) void conv_kernel(float* __restrict__ out)
{
    __shared__ float shQ[16*CVS];     // shQ[h][j] = Q[j-14] (zero-padded)
    __shared__ float shc[NHH*NRR];
    int s = blockIdx.x;
    int tid = threadIdx.x;

    for (int i = tid; i < 16*CVS; i += CVT) {
        int j = i >> 4, h = i & 15;
        int t = j - 14;
        shQ[h*CVS + j] = (t >= 0 && t < NTT)
            ? g_QT[(size_t)t*NSH + s*16 + h] : 0.f;
    }
    for (int i = tid; i < 240; i += CVT) shc[i] = g_cw[s*240 + i];
    __syncthreads();

    int tb = tid * 4;
    if (tb < NTT) {
        float acc0 = 0.f, acc1 = 0.f, acc2 = 0.f, acc3 = 0.f;
        #pragma unroll
        for (int h = 0; h < 16; h++) {
            const float4* qw = (const float4*)(shQ + h*CVS + tb);
            float w[20];
            #pragma unroll
            for (int v = 0; v < 5; v++) {
                float4 q4 = qw[v];
                w[4*v+0] = q4.x; w[4*v+1] = q4.y; w[4*v+2] = q4.z; w[4*v+3] = q4.w;
            }
            #pragma unroll
            for (int d = 0; d < 15; d++) {
                float c = shc[h*15 + d];
                acc0 += w[14 - d] * c;
                acc1 += w[15 - d] * c;
                acc2 += w[16 - d] * c;
                acc3 += w[17 - d] * c;
            }
        }
        out[(tb+0)*NSS + s] = acc0;
        if (tb+1 < NTT) out[(tb+1)*NSS + s] = acc1;
        if (tb+2 < NTT) out[(tb+2)*NSS + s] = acc2;
        if (tb+3 < NTT) out[(tb+3)*NSS + s] = acc3;
    }
}

// =====================================================================
extern "C" void kernel_launch(void* const* d_in, const int* in_sizes, int n_in,
                              void* d_out, int out_size)
{
    const float* x       = (const float*)d_in[0];
    const float* xc      = (const float*)d_in[1];
    const float* fc_W1   = (const float*)d_in[2];
    const float* fc_b1   = (const float*)d_in[3];
    const float* fc_W2   = (const float*)d_in[4];
    const float* fc_b2   = (const float*)d_in[5];
    const float* fcR_W1  = (const float*)d_in[6];
    const float* fcR_b1  = (const float*)d_in[7];
    const float* fcR_W2  = (const float*)d_in[8];
    const float* fcR_b2  = (const float*)d_in[9];
    const float* fcT1_W1 = (const float*)d_in[10];
    const float* fcT1_b1 = (const float*)d_in[11];
    const float* fcT1_W2 = (const float*)d_in[12];
    const float* fcT1_b2 = (const float*)d_in[13];
    const float* fcT2_W1 = (const float*)d_in[14];
    const float* fcT2_b1 = (const float*)d_in[15];
    const float* fcT2_W2 = (const float*)d_in[16];
    const float* fcT2_b2 = (const float*)d_in[17];

    cudaFuncSetAttribute(mlp_kernel, cudaFuncAttributeMaxDynamicSharedMemorySize,
                         SMEM_B_BYTES);

    prep_kernel<<<NSS, 256>>>(xc, fc_W1, fc_b1, fc_W2, fc_b2,
                              fcR_W1, fcR_b1, fcR_W2, fcR_b2,
                              fcT1_W1, fcT1_b1, fcT2_W1, fcT2_b1);

    dim3 gB((NTT + TCHUNK - 1)/TCHUNK, (NSS + 31)/32);
    mlp_kernel<<<gB, 256, SMEM_B_BYTES>>>(x, fcT1_W1, fcT2_W1,
                                          fcT1_W2, fcT1_b2, fcT2_W2, fcT2_b2);

    scan_kernel<<<(NSH + 127)/128, 128>>>();

    conv_kernel<<<NSS, CVT>>>((float*)d_out);
}

// round 4
// speedup vs baseline: 1.4620x; 1.0014x over previous
#include <cuda_runtime.h>
#include <math.h>
#include <stdint.h>

#define NTT 730
#define NSS 2000
#define NHH 16
#define NRR 15
#define NSH (NSS*NHH)          // 32000
#define NTS (NTT*NSS)          // 1460000

// -------- scratch (device globals; no allocation) --------
__device__ __align__(128) float g_base1[256*NSS];
__device__ __align__(128) float g_base2[256*NSS];
__device__ __align__(128) float g_k1[NSH], g_k2[NSH], g_k23[NSH], g_k3[NSH];
__device__ __align__(128) float g_gl[NSH], g_qb[NSH], g_ge1[NSH], g_ge2[NSH];
__device__ __align__(128) float g_cw[NSH*NRR];
__device__ __align__(128) float g_vi[(size_t)NTT*NSH];
__device__ __align__(128) float g_vk[(size_t)NTT*NSH];
__device__ __align__(128) float g_vm[(size_t)NTT*NSH];
__device__ __align__(128) float g_Ps[NTS], g_Pl[NTS], g_E[NTS];
__device__ __align__(128) float g_QT[(size_t)NTT*NSH];

__device__ __forceinline__ float tanh_fast(float x) {
    float e = __expf(2.f * x);
    return 1.f - __fdividef(2.f, e + 1.f);   // err ~1e-7
}
__device__ __forceinline__ float sigmoid_f(float x) {
    return __fdividef(1.f, 1.f + __expf(-x));
}
__device__ __forceinline__ float hsig(float x) {
    return __saturatef(x * (1.f/6.f) + 0.5f);
}

// =====================================================================
// Kernel A: per-basin MLPs (w, wR) + precomputed bases for v1/v2
// =====================================================================
__global__ __launch_bounds__(256) void prep_kernel(
    const float* __restrict__ xc,
    const float* __restrict__ fc_W1,  const float* __restrict__ fc_b1,
    const float* __restrict__ fc_W2,  const float* __restrict__ fc_b2,
    const float* __restrict__ fcR_W1, const float* __restrict__ fcR_b1,
    const float* __restrict__ fcR_W2, const float* __restrict__ fcR_b2,
    const float* __restrict__ fcT1_W1,const float* __restrict__ fcT1_b1,
    const float* __restrict__ fcT2_W1,const float* __restrict__ fcT2_b1)
{
    int s = blockIdx.x;
    int tid = threadIdx.x;
    __shared__ float sxc[32];
    __shared__ float sh_h[256], sh_hR[256];
    __shared__ float sh_w[160], sh_wR[240];
    __shared__ float sh_ga[16];

    if (tid < 32) sxc[tid] = xc[s*32 + tid];
    __syncthreads();

    {   // hidden layers + bases (thread = hidden unit k)
        int k = tid;
        float a0 = fc_b1[k], a1 = fcR_b1[k], a2 = fcT1_b1[k], a3 = fcT2_b1[k];
        #pragma unroll
        for (int g = 0; g < 32; g++) {
            float xg = sxc[g];
            a0 += xg * fc_W1 [k*32 + g];
            a1 += xg * fcR_W1[k*32 + g];
            a2 += xg * fcT1_W1[k*33 + 1 + g];
            a3 += xg * fcT2_W1[k*35 + 3 + g];
        }
        sh_h[k]  = tanh_fast(a0);
        sh_hR[k] = tanh_fast(a1);
        g_base1[k*NSS + s] = a2;   // pre-tanh; LAI term added later
        g_base2[k*NSS + s] = a3;
    }
    __syncthreads();

    int warp = tid >> 5, lane = tid & 31;
    for (int o = warp; o < 400; o += 8) {
        float sum = 0.f;
        if (o < 160) {
            const float* w = fc_W2 + o*256;
            for (int k = lane; k < 256; k += 32) sum += sh_h[k] * w[k];
        } else {
            const float* w = fcR_W2 + (o-160)*256;
            for (int k = lane; k < 256; k += 32) sum += sh_hR[k] * w[k];
        }
        #pragma unroll
        for (int off = 16; off; off >>= 1) sum += __shfl_down_sync(0xffffffffu, sum, off);
        if (lane == 0) {
            if (o < 160) sh_w[o] = sum + fc_b2[o];
            else         sh_wR[o-160] = sum + fcR_b2[o-160];
        }
    }
    __syncthreads();

    if (tid < 16) {
        int h = tid, g = s*16 + h;
        g_k1 [g] = sigmoid_f(sh_w[ 16 + h]);
        g_k2 [g] = sigmoid_f(sh_w[ 32 + h]);
        g_k23[g] = sigmoid_f(sh_w[ 48 + h]);
        g_k3 [g] = sigmoid_f(sh_w[ 64 + h]) * 0.1f;
        g_gl [g] = __expf(sh_w[ 80 + h]) * 2.f;
        g_qb [g] = fmaxf(sh_w[112 + h], 0.f);
        g_ge1[g] = fmaxf(sh_w[128 + h], 0.f);
        g_ge2[g] = fmaxf(sh_w[144 + h], 0.f);
        float m = -1e30f;
        #pragma unroll
        for (int j = 0; j < 16; j++) m = fmaxf(m, sh_w[96 + j]);
        float den = 0.f;
        #pragma unroll
        for (int j = 0; j < 16; j++) den += __expf(sh_w[96 + j] - m);
        sh_ga[h] = __fdividef(__expf(sh_w[96 + h] - m), den);
    }
    __syncthreads();

    if (tid < 240) {
        int h = tid / 15, d = tid - h*15;
        g_cw[(s*16 + h)*15 + d] = sh_ga[h] * fmaxf(sh_wR[h*15 + (14 - d)], 0.f);
    }
}

// =====================================================================
// Kernel B: fused per-(t,s) MLPs, scalar FFMA, 2 timesteps per thread.
// Bases read straight from L1-resident gmem (coalesced [k][s] layout);
// SMEM only holds W2/wc/bias -> 53KB -> 2 CTAs/SM (16 warps).
// =====================================================================
#define TCHUNK 32
#define SMEM_B_FLOATS (256*4 + 256*48 + 48)
#define SMEM_B_BYTES (SMEM_B_FLOATS*4)

__global__ __launch_bounds__(256, 2) void mlp_kernel(
    const float* __restrict__ x,
    const float* __restrict__ fcT1_W1, const float* __restrict__ fcT2_W1,
    const float* __restrict__ fcT1_W2, const float* __restrict__ fcT1_b2,
    const float* __restrict__ fcT2_W2, const float* __restrict__ fcT2_b2)
{
    extern __shared__ float smem[];
    float4* swc   = (float4*)smem;              // [256] {c_LAI, c_R, c_T1, c_T2}
    float*  sw2   = (float*)(swc + 256);        // [256][48]  (k-major, 16B aligned)
    float*  sbias = sw2 + 256*48;               // [48]

    int tid = threadIdx.x;
    int s0 = blockIdx.y * 32;
    int t0 = blockIdx.x * TCHUNK;

    swc[tid] = make_float4(fcT1_W1[tid*33], fcT2_W1[tid*35],
                           fcT2_W1[tid*35 + 1], fcT2_W1[tid*35 + 2]);
    for (int i = tid; i < 256*48; i += 256) {
        int k = i / 48, o = i - k*48;
        sw2[i] = (o < 32) ? fcT1_W2[o*256 + k] : fcT2_W2[(o-32)*256 + k];
    }
    if (tid < 48) sbias[tid] = (tid < 32) ? fcT1_b2[tid] : fcT2_b2[tid - 32];
    __syncthreads();

    int lane = tid & 31, warp = tid >> 5;
    int s = s0 + lane;
    if (s >= NSS) return;     // only barrier is above; safe

    const float* bp1 = g_base1 + s;     // stride NSS per k
    const float* bp2 = g_base2 + s;

    for (int p = 0; p < 2; p++) {
        int ta = t0 + p*16 + warp*2;       // this thread's two timesteps
        if (ta >= NTT) continue;
        int tb = ta + 1;
        bool vb = (tb < NTT);
        int tbl = vb ? tb : ta;            // clamped for loads

        const float* xa = x + (size_t)(ta *NSS + s)*6;
        const float* xb = x + (size_t)(tbl*NSS + s)*6;
        float Pa = xa[0], Ea = xa[1], T1a = xa[2], T2a = xa[3], Ra = xa[4], La = xa[5];
        float Pb = xb[0], Eb = xb[1], T1b = xb[2], T2b = xb[3], Rb = xb[4], Lb = xb[5];

        // snow/rain partition (both timesteps)
        {
            float dn = T2a - T1a;
            float r = (T1a + T2a) / (dn == 0.f ? 1.f : dn);
            r = fminf(fmaxf(r, -1.f), 1.f);
            if ((T1a >= 0.f) || (T2a <= 0.f)) r = 0.f;
            float vp = 1.f - acosf(r) / 3.1415f;
            if (T1a >= 0.f) vp = 1.f;
            if (T2a <= 0.f) vp = 0.f;
            int ts = ta*NSS + s;
            g_Ps[ts] = Pa * (1.f - vp);
            g_Pl[ts] = Pa * vp;
            g_E[ts]  = Ea;
        }
        if (vb) {
            float dn = T2b - T1b;
            float r = (T1b + T2b) / (dn == 0.f ? 1.f : dn);
            r = fminf(fmaxf(r, -1.f), 1.f);
            if ((T1b >= 0.f) || (T2b <= 0.f)) r = 0.f;
            float vp = 1.f - acosf(r) / 3.1415f;
            if (T1b >= 0.f) vp = 1.f;
            if (T2b <= 0.f) vp = 0.f;
            int ts = tb*NSS + s;
            g_Ps[ts] = Pb * (1.f - vp);
            g_Pl[ts] = Pb * vp;
            g_E[ts]  = Eb;
        }

        float accA[48], accB[48];
        #pragma unroll
        for (int o = 0; o < 48; o++) { accA[o] = 0.f; accB[o] = 0.f; }

        #pragma unroll 2
        for (int k = 0; k < 256; k++) {
            float b1  = __ldg(bp1 + k*NSS);
            float b2v = __ldg(bp2 + k*NSS);
            float4 wc = swc[k];
            float h1a = tanh_fast(fmaf(La, wc.x, b1));
            float h1b = tanh_fast(fmaf(Lb, wc.x, b1));
            float h2a = tanh_fast(fmaf(Ra, wc.y, fmaf(T1a, wc.z, fmaf(T2a, wc.w, b2v))));
            float h2b = tanh_fast(fmaf(Rb, wc.y, fmaf(T1b, wc.z, fmaf(T2b, wc.w, b2v))));
            const float4* wv = (const float4*)(sw2 + k*48);
            #pragma unroll
            for (int q = 0; q < 8; q++) {          // outputs 0..31 <- h1
                float4 w4 = wv[q];
                accA[4*q+0] = fmaf(w4.x, h1a, accA[4*q+0]);
                accA[4*q+1] = fmaf(w4.y, h1a, accA[4*q+1]);
                accA[4*q+2] = fmaf(w4.z, h1a, accA[4*q+2]);
                accA[4*q+3] = fmaf(w4.w, h1a, accA[4*q+3]);
                accB[4*q+0] = fmaf(w4.x, h1b, accB[4*q+0]);
                accB[4*q+1] = fmaf(w4.y, h1b, accB[4*q+1]);
                accB[4*q+2] = fmaf(w4.z, h1b, accB[4*q+2]);
                accB[4*q+3] = fmaf(w4.w, h1b, accB[4*q+3]);
            }
            #pragma unroll
            for (int q = 8; q < 12; q++) {         // outputs 32..47 <- h2
                float4 w4 = wv[q];
                accA[4*q+0] = fmaf(w4.x, h2a, accA[4*q+0]);
                accA[4*q+1] = fmaf(w4.y, h2a, accA[4*q+1]);
                accA[4*q+2] = fmaf(w4.z, h2a, accA[4*q+2]);
                accA[4*q+3] = fmaf(w4.w, h2a, accA[4*q+3]);
                accB[4*q+0] = fmaf(w4.x, h2b, accB[4*q+0]);
                accB[4*q+1] = fmaf(w4.y, h2b, accB[4*q+1]);
                accB[4*q+2] = fmaf(w4.z, h2b, accB[4*q+2]);
                accB[4*q+3] = fmaf(w4.w, h2b, accB[4*q+3]);
            }
        }

        size_t baseA = (size_t)ta*NSH + s*16;
        #pragma unroll
        for (int q = 0; q < 4; q++) {
            float4 a;
            a.x = hsig(accA[4*q+0] + sbias[4*q+0]);
            a.y = hsig(accA[4*q+1] + sbias[4*q+1]);
            a.z = hsig(accA[4*q+2] + sbias[4*q+2]);
            a.w = hsig(accA[4*q+3] + sbias[4*q+3]);
            *(float4*)(g_vi + baseA + 4*q) = a;
            float4 b;
            b.x = hsig(accA[16+4*q+0] + sbias[16+4*q+0]);
            b.y = hsig(accA[16+4*q+1] + sbias[16+4*q+1]);
            b.z = hsig(accA[16+4*q+2] + sbias[16+4*q+2]);
            b.w = hsig(accA[16+4*q+3] + sbias[16+4*q+3]);
            *(float4*)(g_vk + baseA + 4*q) = b;
            float4 c;
            c.x = __expf(2.f*(accA[32+4*q+0] + sbias[32+4*q+0]));
            c.y = __expf(2.f*(accA[32+4*q+1] + sbias[32+4*q+1]));
            c.z = __expf(2.f*(accA[32+4*q+2] + sbias[32+4*q+2]));
            c.w = __expf(2.f*(accA[32+4*q+3] + sbias[32+4*q+3]));
            *(float4*)(g_vm + baseA + 4*q) = c;
        }
        if (vb) {
            size_t baseB = (size_t)tb*NSH + s*16;
            #pragma unroll
            for (int q = 0; q < 4; q++) {
                float4 a;
                a.x = hsig(accB[4*q+0] + sbias[4*q+0]);
                a.y = hsig(accB[4*q+1] + sbias[4*q+1]);
                a.z = hsig(accB[4*q+2] + sbias[4*q+2]);
                a.w = hsig(accB[4*q+3] + sbias[4*q+3]);
                *(float4*)(g_vi + baseB + 4*q) = a;
                float4 b;
                b.x = hsig(accB[16+4*q+0] + sbias[16+4*q+0]);
                b.y = hsig(accB[16+4*q+1] + sbias[16+4*q+1]);
                b.z = hsig(accB[16+4*q+2] + sbias[16+4*q+2]);
                b.w = hsig(accB[16+4*q+3] + sbias[16+4*q+3]);
                *(float4*)(g_vk + baseB + 4*q) = b;
                float4 c;
                c.x = __expf(2.f*(accB[32+4*q+0] + sbias[32+4*q+0]));
                c.y = __expf(2.f*(accB[32+4*q+1] + sbias[32+4*q+1]));
                c.z = __expf(2.f*(accB[32+4*q+2] + sbias[32+4*q+2]));
                c.w = __expf(2.f*(accB[32+4*q+3] + sbias[32+4*q+3]));
                *(float4*)(g_vm + baseB + 4*q) = c;
            }
        }
    }
}

// =====================================================================
// Kernel C: sequential reservoir scan; thread = (s,h)
// =====================================================================
__global__ __launch_bounds__(128) void scan_kernel()
{
    int g = blockIdx.x * 128 + threadIdx.x;
    if (g >= NSH) return;
    int s = g >> 4;
    float k1 = g_k1[g], k2 = g_k2[g], k23 = g_k23[g], k3 = g_k3[g];
    float gl = g_gl[g], qb = g_qb[g], ge1 = g_ge1[g], ge2 = g_ge2[g];
    float S0 = 0.f, Sv = 0.f, S2 = 0.f, S3 = 0.f;

    #pragma unroll 4
    for (int t = 0; t < NTT; t++) {
        int ts = t*NSS + s;
        size_t tg = (size_t)t*NSH + g;
        float Ps = g_Ps[ts], Pl = g_Pl[ts], E = g_E[ts];
        float vi = g_vi[tg], vk = g_vk[tg], vm = g_vm[tg];

        float H0  = S0 + Ps;
        float qSm = fminf(H0, vm);
        float Hv  = fmaxf(Sv + Pl*(1.f - vi) - E*ge1, 0.f);
        float qv  = Sv * vk;
        float H2  = fmaxf(S2 + qSm + qv - E*ge2 + Pl*vi, 0.f);
        float x1  = H2 - gl;
        float Q1  = (x1 > 0.f) ? exp2f(k1 * __log2f(x1)) : 0.f;
        float q2  = fminf(H2, gl) * k2;
        float Q2  = q2 * (1.f - k23);
        float H3  = S3 + q2 * k23;
        float Q3  = H3 * k3 + qb;

        S0 = H0 - qSm;
        Sv = Hv - qv;
        S2 = H2 - Q1 - q2;
        S3 = H3 - Q3;
        g_QT[tg] = Q1 + Q2 + Q3;
    }
}

// =====================================================================
// Kernel D: causal depthwise conv + head-sum, register-blocked 4 t/thread
// =====================================================================
#define CVT 192
#define CVS 788                       // row stride (floats): 16B-aligned, low conflicts
__global__ __launch_bounds__(CVT) void conv_kernel(float* __restrict__ out)
{
    __shared__ float shQ[16*CVS];     // shQ[h][j] = Q[j-14] (zero-padded)
    __shared__ float shc[NHH*NRR];
    int s = blockIdx.x;
    int tid = threadIdx.x;

    for (int i = tid; i < 16*CVS; i += CVT) {
        int j = i >> 4, h = i & 15;
        int t = j - 14;
        shQ[h*CVS + j] = (t >= 0 && t < NTT)
            ? g_QT[(size_t)t*NSH + s*16 + h] : 0.f;
    }
    for (int i = tid; i < 240; i += CVT) shc[i] = g_cw[s*240 + i];
    __syncthreads();

    int tb = tid * 4;
    if (tb < NTT) {
        float acc0 = 0.f, acc1 = 0.f, acc2 = 0.f, acc3 = 0.f;
        #pragma unroll
        for (int h = 0; h < 16; h++) {
            const float4* qw = (const float4*)(shQ + h*CVS + tb);
            float w[20];
            #pragma unroll
            for (int v = 0; v < 5; v++) {
                float4 q4 = qw[v];
                w[4*v+0] = q4.x; w[4*v+1] = q4.y; w[4*v+2] = q4.z; w[4*v+3] = q4.w;
            }
            #pragma unroll
            for (int d = 0; d < 15; d++) {
                float c = shc[h*15 + d];
                acc0 += w[14 - d] * c;
                acc1 += w[15 - d] * c;
                acc2 += w[16 - d] * c;
                acc3 += w[17 - d] * c;
            }
        }
        out[(tb+0)*NSS + s] = acc0;
        if (tb+1 < NTT) out[(tb+1)*NSS + s] = acc1;
        if (tb+2 < NTT) out[(tb+2)*NSS + s] = acc2;
        if (tb+3 < NTT) out[(tb+3)*NSS + s] = acc3;
    }
}

// =====================================================================
extern "C" void kernel_launch(void* const* d_in, const int* in_sizes, int n_in,
                              void* d_out, int out_size)
{
    const float* x       = (const float*)d_in[0];
    const float* xc      = (const float*)d_in[1];
    const float* fc_W1   = (const float*)d_in[2];
    const float* fc_b1   = (const float*)d_in[3];
    const float* fc_W2   = (const float*)d_in[4];
    const float* fc_b2   = (const float*)d_in[5];
    const float* fcR_W1  = (const float*)d_in[6];
    const float* fcR_b1  = (const float*)d_in[7];
    const float* fcR_W2  = (const float*)d_in[8];
    const float* fcR_b2  = (const float*)d_in[9];
    const float* fcT1_W1 = (const float*)d_in[10];
    const float* fcT1_b1 = (const float*)d_in[11];
    const float* fcT1_W2 = (const float*)d_in[12];
    const float* fcT1_b2 = (const float*)d_in[13];
    const float* fcT2_W1 = (const float*)d_in[14];
    const float* fcT2_b1 = (const float*)d_in[15];
    const float* fcT2_W2 = (const float*)d_in[16];
    const float* fcT2_b2 = (const float*)d_in[17];

    cudaFuncSetAttribute(mlp_kernel, cudaFuncAttributeMaxDynamicSharedMemorySize,
                         SMEM_B_BYTES);

    prep_kernel<<<NSS, 256>>>(xc, fc_W1, fc_b1, fc_W2, fc_b2,
                              fcR_W1, fcR_b1, fcR_W2, fcR_b2,
                              fcT1_W1, fcT1_b1, fcT2_W1, fcT2_b1);

    dim3 gB((NTT + TCHUNK - 1)/TCHUNK, (NSS + 31)/32);
    mlp_kernel<<<gB, 256, SMEM_B_BYTES>>>(x, fcT1_W1, fcT2_W1,
                                          fcT1_W2, fcT1_b2, fcT2_W2, fcT2_b2);

    scan_kernel<<<(NSH + 127)/128, 128>>>();

    conv_kernel<<<NSS, CVT>>>((float*)d_out);
}

// round 5
// speedup vs baseline: 2.0120x; 1.3762x over previous
#include <cuda_runtime.h>
#include <math.h>
#include <stdint.h>

#define NTT 730
#define NSS 2000
#define NHH 16
#define NRR 15
#define NSH (NSS*NHH)          // 32000
#define NTS (NTT*NSS)          // 1460000

#define L2E2 2.8853900817779268f   // 2*log2(e)

// -------- scratch (device globals; no allocation) --------
__device__ __align__(128) float  g_b1T[NSS*256];     // tanh-prescaled, [s][k]
__device__ __align__(128) float  g_b2T[NSS*256];
__device__ __align__(128) float4 g_wc4[256];         // prescaled first-layer x-coeffs
__device__ __align__(128) float2 g_W2p[32*4*49];     // tf32-packed W2 pairs (k,k+4)
__device__ __align__(128) float  g_sbias[48];
__device__ __align__(128) float g_k1[NSH], g_k2[NSH], g_k23[NSH], g_k3[NSH];
__device__ __align__(128) float g_gl[NSH], g_qb[NSH], g_ge1[NSH], g_ge2[NSH];
__device__ __align__(128) float g_cw[NSH*NRR];
__device__ __align__(128) float g_vi[(size_t)NTT*NSH];
__device__ __align__(128) float g_vk[(size_t)NTT*NSH];
__device__ __align__(128) float g_vm[(size_t)NTT*NSH];
__device__ __align__(128) float g_Ps[NTS], g_Pl[NTS], g_E[NTS];
__device__ __align__(128) float g_QT[(size_t)NTT*NSH];

__device__ __forceinline__ float tanh_fast(float x) {
    float e = __expf(2.f * x);
    return 1.f - __fdividef(2.f, e + 1.f);
}
__device__ __forceinline__ float sigmoid_f(float x) {
    return __fdividef(1.f, 1.f + __expf(-x));
}
__device__ __forceinline__ float hsig(float x) {
    return __saturatef(x * (1.f/6.f) + 0.5f);
}
// tanh on pre-scaled argument t = 2*log2(e)*x
__device__ __forceinline__ float tanhe(float t) {
    float e; asm("ex2.approx.f32 %0, %1;" : "=f"(e) : "f"(t));
    float r; asm("rcp.approx.f32 %0, %1;" : "=f"(r) : "f"(e + 1.f));
    return fmaf(-2.f, r, 1.f);
}
__device__ __forceinline__ float ex2f(float t) {
    float e; asm("ex2.approx.f32 %0, %1;" : "=f"(e) : "f"(t));
    return e;
}
__device__ __forceinline__ uint32_t cvt_tf32(float x) {
    uint32_t r; asm("cvt.rna.tf32.f32 %0, %1;" : "=r"(r) : "f"(x));
    return r;
}
__device__ __forceinline__ void mma8(float* d, const uint32_t* a, float2 b) {
    uint32_t b0 = __float_as_uint(b.x), b1 = __float_as_uint(b.y);
    asm("mma.sync.aligned.m16n8k8.row.col.f32.tf32.tf32.f32 "
        "{%0,%1,%2,%3}, {%4,%5,%6,%7}, {%8,%9}, {%0,%1,%2,%3};"
        : "+f"(d[0]), "+f"(d[1]), "+f"(d[2]), "+f"(d[3])
        : "r"(a[0]), "r"(a[1]), "r"(a[2]), "r"(a[3]), "r"(b0), "r"(b1));
}

// =====================================================================
// Kernel A: per-basin MLPs (w, wR) + prescaled transposed bases
// =====================================================================
__global__ __launch_bounds__(256) void prep_kernel(
    const float* __restrict__ xc,
    const float* __restrict__ fc_W1,  const float* __restrict__ fc_b1,
    const float* __restrict__ fc_W2,  const float* __restrict__ fc_b2,
    const float* __restrict__ fcR_W1, const float* __restrict__ fcR_b1,
    const float* __restrict__ fcR_W2, const float* __restrict__ fcR_b2,
    const float* __restrict__ fcT1_W1,const float* __restrict__ fcT1_b1,
    const float* __restrict__ fcT2_W1,const float* __restrict__ fcT2_b1)
{
    int s = blockIdx.x;
    int tid = threadIdx.x;
    __shared__ float sxc[32];
    __shared__ float sh_h[256], sh_hR[256];
    __shared__ float sh_w[160], sh_wR[240];
    __shared__ float sh_ga[16];

    if (tid < 32) sxc[tid] = xc[s*32 + tid];
    __syncthreads();

    {
        int k = tid;
        float a0 = fc_b1[k], a1 = fcR_b1[k], a2 = fcT1_b1[k], a3 = fcT2_b1[k];
        #pragma unroll
        for (int g = 0; g < 32; g++) {
            float xg = sxc[g];
            a0 += xg * fc_W1 [k*32 + g];
            a1 += xg * fcR_W1[k*32 + g];
            a2 += xg * fcT1_W1[k*33 + 1 + g];
            a3 += xg * fcT2_W1[k*35 + 3 + g];
        }
        sh_h[k]  = tanh_fast(a0);
        sh_hR[k] = tanh_fast(a1);
        g_b1T[s*256 + k] = a2 * L2E2;   // prescaled for tanhe
        g_b2T[s*256 + k] = a3 * L2E2;
    }
    __syncthreads();

    int warp = tid >> 5, lane = tid & 31;
    for (int o = warp; o < 400; o += 8) {
        float sum = 0.f;
        if (o < 160) {
            const float* w = fc_W2 + o*256;
            for (int k = lane; k < 256; k += 32) sum += sh_h[k] * w[k];
        } else {
            const float* w = fcR_W2 + (o-160)*256;
            for (int k = lane; k < 256; k += 32) sum += sh_hR[k] * w[k];
        }
        #pragma unroll
        for (int off = 16; off; off >>= 1) sum += __shfl_down_sync(0xffffffffu, sum, off);
        if (lane == 0) {
            if (o < 160) sh_w[o] = sum + fc_b2[o];
            else         sh_wR[o-160] = sum + fcR_b2[o-160];
        }
    }
    __syncthreads();

    if (tid < 16) {
        int h = tid, g = s*16 + h;
        g_k1 [g] = sigmoid_f(sh_w[ 16 + h]);
        g_k2 [g] = sigmoid_f(sh_w[ 32 + h]);
        g_k23[g] = sigmoid_f(sh_w[ 48 + h]);
        g_k3 [g] = sigmoid_f(sh_w[ 64 + h]) * 0.1f;
        g_gl [g] = __expf(sh_w[ 80 + h]) * 2.f;
        g_qb [g] = fmaxf(sh_w[112 + h], 0.f);
        g_ge1[g] = fmaxf(sh_w[128 + h], 0.f);
        g_ge2[g] = fmaxf(sh_w[144 + h], 0.f);
        float m = -1e30f;
        #pragma unroll
        for (int j = 0; j < 16; j++) m = fmaxf(m, sh_w[96 + j]);
        float den = 0.f;
        #pragma unroll
        for (int j = 0; j < 16; j++) den += __expf(sh_w[96 + j] - m);
        sh_ga[h] = __fdividef(__expf(sh_w[96 + h] - m), den);
    }
    __syncthreads();

    if (tid < 240) {
        int h = tid / 15, d = tid - h*15;
        g_cw[(s*16 + h)*15 + d] = sh_ga[h] * fmaxf(sh_wR[h*15 + (14 - d)], 0.f);
    }
}

// =====================================================================
// Kernel A2: pack W2 into tf32 (k,k+4) float2 pairs + wc/bias tables
// one block, 256 threads
// =====================================================================
__global__ __launch_bounds__(256) void pack_kernel(
    const float* __restrict__ fcT1_W1, const float* __restrict__ fcT2_W1,
    const float* __restrict__ fcT1_W2, const float* __restrict__ fcT1_b2,
    const float* __restrict__ fcT2_W2, const float* __restrict__ fcT2_b2)
{
    int tid = threadIdx.x;
    {   // wc table (prescaled)
        int k = tid;
        g_wc4[k] = make_float4(fcT1_W1[k*33]     * L2E2,
                               fcT2_W1[k*35]     * L2E2,
                               fcT2_W1[k*35 + 1] * L2E2,
                               fcT2_W1[k*35 + 2] * L2E2);
    }
    if (tid < 48) g_sbias[tid] = (tid < 32) ? fcT1_b2[tid] : fcT2_b2[tid - 32];

    for (int idx = tid; idx < 32*4*48; idx += 256) {
        int j = idx / 192, rem = idx - j*192;
        int c = rem / 48,  o  = rem - c*48;
        int k0 = 8*j + c, k1 = k0 + 4;
        float w0 = (o < 32) ? fcT1_W2[o*256 + k0] : fcT2_W2[(o-32)*256 + k0];
        float w1 = (o < 32) ? fcT1_W2[o*256 + k1] : fcT2_W2[(o-32)*256 + k1];
        g_W2p[(j*4 + c)*49 + o] =
            make_float2(__uint_as_float(cvt_tf32(w0)), __uint_as_float(cvt_tf32(w1)));
    }
}

// =====================================================================
// Kernel B: tensor-core MLP. warp = 16 timesteps x 1 basin.
// block = 8 warps (8 basins), grid = (46 t-tiles, 250 s-groups)
// =====================================================================
#define SMEM_W2P_F (32*4*49*2)          // 12544 floats
#define SMEM_MLP_BYTES ((SMEM_W2P_F + 256*4 + 8*512 + 48) * 4)   // 70848

__global__ __launch_bounds__(256) void mlp_kernel(const float* __restrict__ x)
{
    extern __shared__ float smem[];
    float2* sW2p  = (float2*)smem;                    // [32*4*49]
    float4* swc   = (float4*)(smem + SMEM_W2P_F);     // [256]
    float*  sbase = smem + SMEM_W2P_F + 256*4;        // [8][512]
    float*  sbias = sbase + 8*512;                    // [48]

    int tid = threadIdx.x;
    int w = tid >> 5, lane = tid & 31;
    int c = lane & 3, r = lane >> 2;

    // ---- prologue fills ----
    {
        const uint4* src = (const uint4*)g_W2p;
        uint4* dst = (uint4*)sW2p;
        for (int i = tid; i < SMEM_W2P_F/4; i += 256) dst[i] = src[i];
        swc[tid] = g_wc4[tid];
        if (tid < 48) sbias[tid] = g_sbias[tid];
    }
    int s = blockIdx.y*8 + w;
    {
        float* sb = sbase + w*512;
        const float4* b1s = (const float4*)(g_b1T + s*256);
        const float4* b2s = (const float4*)(g_b2T + s*256);
        for (int i = lane; i < 64; i += 32) {
            ((float4*)sb)[i]        = b1s[i];
            ((float4*)(sb+256))[i]  = b2s[i];
        }
    }
    __syncthreads();

    int t0 = blockIdx.x * 16;
    int tA = t0 + r;              // always < NTT (max 727)
    int tB = tA + 8;              // may overflow on last tile
    int tBl = (tB < NTT) ? tB : (NTT-1);

    const float* xA = x + (size_t)(tA *NSS + s)*6;
    const float* xB = x + (size_t)(tBl*NSS + s)*6;
    float PA = xA[0], EA = xA[1], T1A = xA[2], T2A = xA[3], RA = xA[4], LA = xA[5];
    float PB = xB[0], EB = xB[1], T1B = xB[2], T2B = xB[3], RB = xB[4], LB = xB[5];

    // snow/rain partition: one thread per row (c == 0)
    if (c == 0) {
        {
            float dn = T2A - T1A;
            float rr = (T1A + T2A) / (dn == 0.f ? 1.f : dn);
            rr = fminf(fmaxf(rr, -1.f), 1.f);
            if ((T1A >= 0.f) || (T2A <= 0.f)) rr = 0.f;
            float vp = 1.f - acosf(rr) / 3.1415f;
            if (T1A >= 0.f) vp = 1.f;
            if (T2A <= 0.f) vp = 0.f;
            int ts = tA*NSS + s;
            g_Ps[ts] = PA * (1.f - vp);
            g_Pl[ts] = PA * vp;
            g_E[ts]  = EA;
        }
        if (tB < NTT) {
            float dn = T2B - T1B;
            float rr = (T1B + T2B) / (dn == 0.f ? 1.f : dn);
            rr = fminf(fmaxf(rr, -1.f), 1.f);
            if ((T1B >= 0.f) || (T2B <= 0.f)) rr = 0.f;
            float vp = 1.f - acosf(rr) / 3.1415f;
            if (T1B >= 0.f) vp = 1.f;
            if (T2B <= 0.f) vp = 0.f;
            int ts = tB*NSS + s;
            g_Ps[ts] = PB * (1.f - vp);
            g_Pl[ts] = PB * vp;
            g_E[ts]  = EB;
        }
    }

    float dd[6][4];
    #pragma unroll
    for (int g = 0; g < 6; g++)
        #pragma unroll
        for (int i = 0; i < 4; i++) dd[g][i] = 0.f;

    const float* sb1 = sbase + w*512;
    const float* sb2 = sb1 + 256;

    #pragma unroll 2
    for (int j = 0; j < 32; j++) {
        int k0 = j*8 + c;
        float b1k0 = sb1[k0], b1k1 = sb1[k0+4];
        float b2k0 = sb2[k0], b2k1 = sb2[k0+4];
        float4 w0 = swc[k0], w1 = swc[k0+4];

        // A fragments: a0=(rowA,k0) a1=(rowB,k0) a2=(rowA,k1) a3=(rowB,k1)
        uint32_t aa1[4], aa2[4];
        aa1[0] = cvt_tf32(tanhe(fmaf(LA, w0.x, b1k0)));
        aa1[1] = cvt_tf32(tanhe(fmaf(LB, w0.x, b1k0)));
        aa1[2] = cvt_tf32(tanhe(fmaf(LA, w1.x, b1k1)));
        aa1[3] = cvt_tf32(tanhe(fmaf(LB, w1.x, b1k1)));
        aa2[0] = cvt_tf32(tanhe(fmaf(RA, w0.y, fmaf(T1A, w0.z, fmaf(T2A, w0.w, b2k0)))));
        aa2[1] = cvt_tf32(tanhe(fmaf(RB, w0.y, fmaf(T1B, w0.z, fmaf(T2B, w0.w, b2k0)))));
        aa2[2] = cvt_tf32(tanhe(fmaf(RA, w1.y, fmaf(T1A, w1.z, fmaf(T2A, w1.w, b2k1)))));
        aa2[3] = cvt_tf32(tanhe(fmaf(RB, w1.y, fmaf(T1B, w1.z, fmaf(T2B, w1.w, b2k1)))));

        const float2* Wrow = sW2p + (j*4 + c)*49;
        #pragma unroll
        for (int g = 0; g < 4; g++) mma8(dd[g], aa1, Wrow[8*g + r]);
        #pragma unroll
        for (int g = 4; g < 6; g++) mma8(dd[g], aa2, Wrow[8*g + r]);
    }

    // epilogue: thread holds cols (8g+2c, 8g+2c+1) for rows tA, tB
    #pragma unroll
    for (int g = 0; g < 6; g++) {
        int o = 8*g + 2*c;
        float bi0 = sbias[o], bi1 = sbias[o+1];
        float vA0 = dd[g][0] + bi0, vA1 = dd[g][1] + bi1;
        float vB0 = dd[g][2] + bi0, vB1 = dd[g][3] + bi1;
        float2 oA, oB;
        float* arr;
        if (g < 4) {
            oA = make_float2(hsig(vA0), hsig(vA1));
            oB = make_float2(hsig(vB0), hsig(vB1));
            arr = (g < 2) ? g_vi : g_vk;
        } else {
            oA = make_float2(ex2f(vA0*L2E2), ex2f(vA1*L2E2));
            oB = make_float2(ex2f(vB0*L2E2), ex2f(vB1*L2E2));
            arr = g_vm;
        }
        int h = o & 15;
        *(float2*)(arr + (size_t)tA*NSH + s*16 + h) = oA;
        if (tB < NTT)
            *(float2*)(arr + (size_t)tB*NSH + s*16 + h) = oB;
    }
}

// =====================================================================
// Kernel C: sequential reservoir scan; thread = (s,h)
// =====================================================================
__global__ __launch_bounds__(128) void scan_kernel()
{
    int g = blockIdx.x * 128 + threadIdx.x;
    if (g >= NSH) return;
    int s = g >> 4;
    float k1 = g_k1[g], k2 = g_k2[g], k23 = g_k23[g], k3 = g_k3[g];
    float gl = g_gl[g], qb = g_qb[g], ge1 = g_ge1[g], ge2 = g_ge2[g];
    float S0 = 0.f, Sv = 0.f, S2 = 0.f, S3 = 0.f;

    #pragma unroll 4
    for (int t = 0; t < NTT; t++) {
        int ts = t*NSS + s;
        size_t tg = (size_t)t*NSH + g;
        float Ps = g_Ps[ts], Pl = g_Pl[ts], E = g_E[ts];
        float vi = g_vi[tg], vk = g_vk[tg], vm = g_vm[tg];

        float H0  = S0 + Ps;
        float qSm = fminf(H0, vm);
        float Hv  = fmaxf(Sv + Pl*(1.f - vi) - E*ge1, 0.f);
        float qv  = Sv * vk;
        float H2  = fmaxf(S2 + qSm + qv - E*ge2 + Pl*vi, 0.f);
        float x1  = H2 - gl;
        float Q1  = (x1 > 0.f) ? exp2f(k1 * __log2f(x1)) : 0.f;
        float q2  = fminf(H2, gl) * k2;
        float Q2  = q2 * (1.f - k23);
        float H3  = S3 + q2 * k23;
        float Q3  = H3 * k3 + qb;

        S0 = H0 - qSm;
        Sv = Hv - qv;
        S2 = H2 - Q1 - q2;
        S3 = H3 - Q3;
        g_QT[tg] = Q1 + Q2 + Q3;
    }
}

// =====================================================================
// Kernel D: causal depthwise conv + head-sum, register-blocked 4 t/thread
// =====================================================================
#define CVT 192
#define CVS 788
__global__ __launch_bounds__(CVT) void conv_kernel(float* __restrict__ out)
{
    __shared__ float shQ[16*CVS];
    __shared__ float shc[NHH*NRR];
    int s = blockIdx.x;
    int tid = threadIdx.x;

    for (int i = tid; i < 16*CVS; i += CVT) {
        int j = i >> 4, h = i & 15;
        int t = j - 14;
        shQ[h*CVS + j] = (t >= 0 && t < NTT)
            ? g_QT[(size_t)t*NSH + s*16 + h] : 0.f;
    }
    for (int i = tid; i < 240; i += CVT) shc[i] = g_cw[s*240 + i];
    __syncthreads();

    int tb = tid * 4;
    if (tb < NTT) {
        float acc0 = 0.f, acc1 = 0.f, acc2 = 0.f, acc3 = 0.f;
        #pragma unroll
        for (int h = 0; h < 16; h++) {
            const float4* qw = (const float4*)(shQ + h*CVS + tb);
            float wv[20];
            #pragma unroll
            for (int v = 0; v < 5; v++) {
                float4 q4 = qw[v];
                wv[4*v+0] = q4.x; wv[4*v+1] = q4.y; wv[4*v+2] = q4.z; wv[4*v+3] = q4.w;
            }
            #pragma unroll
            for (int d = 0; d < 15; d++) {
                float cc = shc[h*15 + d];
                acc0 += wv[14 - d] * cc;
                acc1 += wv[15 - d] * cc;
                acc2 += wv[16 - d] * cc;
                acc3 += wv[17 - d] * cc;
            }
        }
        out[(tb+0)*NSS + s] = acc0;
        if (tb+1 < NTT) out[(tb+1)*NSS + s] = acc1;
        if (tb+2 < NTT) out[(tb+2)*NSS + s] = acc2;
        if (tb+3 < NTT) out[(tb+3)*NSS + s] = acc3;
    }
}

// =====================================================================
extern "C" void kernel_launch(void* const* d_in, const int* in_sizes, int n_in,
                              void* d_out, int out_size)
{
    const float* x       = (const float*)d_in[0];
    const float* xc      = (const float*)d_in[1];
    const float* fc_W1   = (const float*)d_in[2];
    const float* fc_b1   = (const float*)d_in[3];
    const float* fc_W2   = (const float*)d_in[4];
    const float* fc_b2   = (const float*)d_in[5];
    const float* fcR_W1  = (const float*)d_in[6];
    const float* fcR_b1  = (const float*)d_in[7];
    const float* fcR_W2  = (const float*)d_in[8];
    const float* fcR_b2  = (const float*)d_in[9];
    const float* fcT1_W1 = (const float*)d_in[10];
    const float* fcT1_b1 = (const float*)d_in[11];
    const float* fcT1_W2 = (const float*)d_in[12];
    const float* fcT1_b2 = (const float*)d_in[13];
    const float* fcT2_W1 = (const float*)d_in[14];
    const float* fcT2_b1 = (const float*)d_in[15];
    const float* fcT2_W2 = (const float*)d_in[16];
    const float* fcT2_b2 = (const float*)d_in[17];

    cudaFuncSetAttribute(mlp_kernel, cudaFuncAttributeMaxDynamicSharedMemorySize,
                         SMEM_MLP_BYTES);

    prep_kernel<<<NSS, 256>>>(xc, fc_W1, fc_b1, fc_W2, fc_b2,
                              fcR_W1, fcR_b1, fcR_W2, fcR_b2,
                              fcT1_W1, fcT1_b1, fcT2_W1, fcT2_b1);

    pack_kernel<<<1, 256>>>(fcT1_W1, fcT2_W1, fcT1_W2, fcT1_b2, fcT2_W2, fcT2_b2);

    dim3 gB((NTT + 15)/16, NSS/8);
    mlp_kernel<<<gB, 256, SMEM_MLP_BYTES>>>(x);

    scan_kernel<<<(NSH + 127)/128, 128>>>();

    conv_kernel<<<NSS, CVT>>>((float*)d_out);
}

// round 6
// speedup vs baseline: 2.5473x; 1.2660x over previous
#include <cuda_runtime.h>
#include <math.h>
#include <stdint.h>

#define NTT 730
#define NSS 2000
#define NHH 16
#define NRR 15
#define NSH (NSS*NHH)          // 32000
#define NTS (NTT*NSS)          // 1460000

#define L2E2 2.8853900817779268f   // 2*log2(e)

// -------- scratch (device globals; no allocation) --------
__device__ __align__(128) float  g_b1T[NSS*256];     // tanh-prescaled, [s][k]
__device__ __align__(128) float  g_b2T[NSS*256];
__device__ __align__(128) float4 g_wc4[256];         // prescaled first-layer x-coeffs
__device__ __align__(128) float2 g_W2p[32*4*49];     // tf32-packed W2 pairs (k,k+4)
__device__ __align__(128) float  g_sbias[48];
__device__ __align__(128) float g_k1[NSH], g_k2[NSH], g_k23[NSH], g_k3[NSH];
__device__ __align__(128) float g_gl[NSH], g_qb[NSH], g_ge1[NSH], g_ge2[NSH];
__device__ __align__(128) float g_cw[NSH*NRR];
__device__ __align__(128) float g_vi[(size_t)NTT*NSH];
__device__ __align__(128) float g_vk[(size_t)NTT*NSH];
__device__ __align__(128) float g_vm[(size_t)NTT*NSH];
__device__ __align__(128) float g_Ps[NTS], g_Pl[NTS], g_E[NTS];
__device__ __align__(128) float g_QT[(size_t)NTT*NSH];

__device__ __forceinline__ float tanh_fast(float x) {
    float e = __expf(2.f * x);
    return 1.f - __fdividef(2.f, e + 1.f);
}
__device__ __forceinline__ float sigmoid_f(float x) {
    return __fdividef(1.f, 1.f + __expf(-x));
}
__device__ __forceinline__ float hsig(float x) {
    return __saturatef(x * (1.f/6.f) + 0.5f);
}
// tanh on pre-scaled argument t = 2*log2(e)*x
__device__ __forceinline__ float tanhe(float t) {
    float e; asm("ex2.approx.f32 %0, %1;" : "=f"(e) : "f"(t));
    float r; asm("rcp.approx.f32 %0, %1;" : "=f"(r) : "f"(e + 1.f));
    return fmaf(-2.f, r, 1.f);
}
__device__ __forceinline__ float ex2f(float t) {
    float e; asm("ex2.approx.f32 %0, %1;" : "=f"(e) : "f"(t));
    return e;
}
__device__ __forceinline__ uint32_t cvt_tf32(float x) {
    uint32_t r; asm("cvt.rna.tf32.f32 %0, %1;" : "=r"(r) : "f"(x));
    return r;
}
__device__ __forceinline__ void mma8(float* d, const uint32_t* a, float2 b) {
    uint32_t b0 = __float_as_uint(b.x), b1 = __float_as_uint(b.y);
    asm("mma.sync.aligned.m16n8k8.row.col.f32.tf32.tf32.f32 "
        "{%0,%1,%2,%3}, {%4,%5,%6,%7}, {%8,%9}, {%0,%1,%2,%3};"
        : "+f"(d[0]), "+f"(d[1]), "+f"(d[2]), "+f"(d[3])
        : "r"(a[0]), "r"(a[1]), "r"(a[2]), "r"(a[3]), "r"(b0), "r"(b1));
}

// =====================================================================
// Kernel A: per-basin MLPs (w, wR) + prescaled transposed bases
// =====================================================================
__global__ __launch_bounds__(256) void prep_kernel(
    const float* __restrict__ xc,
    const float* __restrict__ fc_W1,  const float* __restrict__ fc_b1,
    const float* __restrict__ fc_W2,  const float* __restrict__ fc_b2,
    const float* __restrict__ fcR_W1, const float* __restrict__ fcR_b1,
    const float* __restrict__ fcR_W2, const float* __restrict__ fcR_b2,
    const float* __restrict__ fcT1_W1,const float* __restrict__ fcT1_b1,
    const float* __restrict__ fcT2_W1,const float* __restrict__ fcT2_b1)
{
    int s = blockIdx.x;
    int tid = threadIdx.x;
    __shared__ float sxc[32];
    __shared__ float sh_h[256], sh_hR[256];
    __shared__ float sh_w[160], sh_wR[240];
    __shared__ float sh_ga[16];

    if (tid < 32) sxc[tid] = xc[s*32 + tid];
    __syncthreads();

    {
        int k = tid;
        float a0 = fc_b1[k], a1 = fcR_b1[k], a2 = fcT1_b1[k], a3 = fcT2_b1[k];
        #pragma unroll
        for (int g = 0; g < 32; g++) {
            float xg = sxc[g];
            a0 += xg * fc_W1 [k*32 + g];
            a1 += xg * fcR_W1[k*32 + g];
            a2 += xg * fcT1_W1[k*33 + 1 + g];
            a3 += xg * fcT2_W1[k*35 + 3 + g];
        }
        sh_h[k]  = tanh_fast(a0);
        sh_hR[k] = tanh_fast(a1);
        g_b1T[s*256 + k] = a2 * L2E2;   // prescaled for tanhe
        g_b2T[s*256 + k] = a3 * L2E2;
    }
    __syncthreads();

    int warp = tid >> 5, lane = tid & 31;
    for (int o = warp; o < 400; o += 8) {
        float sum = 0.f;
        if (o < 160) {
            const float* w = fc_W2 + o*256;
            for (int k = lane; k < 256; k += 32) sum += sh_h[k] * w[k];
        } else {
            const float* w = fcR_W2 + (o-160)*256;
            for (int k = lane; k < 256; k += 32) sum += sh_hR[k] * w[k];
        }
        #pragma unroll
        for (int off = 16; off; off >>= 1) sum += __shfl_down_sync(0xffffffffu, sum, off);
        if (lane == 0) {
            if (o < 160) sh_w[o] = sum + fc_b2[o];
            else         sh_wR[o-160] = sum + fcR_b2[o-160];
        }
    }
    __syncthreads();

    if (tid < 16) {
        int h = tid, g = s*16 + h;
        g_k1 [g] = sigmoid_f(sh_w[ 16 + h]);
        g_k2 [g] = sigmoid_f(sh_w[ 32 + h]);
        g_k23[g] = sigmoid_f(sh_w[ 48 + h]);
        g_k3 [g] = sigmoid_f(sh_w[ 64 + h]) * 0.1f;
        g_gl [g] = __expf(sh_w[ 80 + h]) * 2.f;
        g_qb [g] = fmaxf(sh_w[112 + h], 0.f);
        g_ge1[g] = fmaxf(sh_w[128 + h], 0.f);
        g_ge2[g] = fmaxf(sh_w[144 + h], 0.f);
        float m = -1e30f;
        #pragma unroll
        for (int j = 0; j < 16; j++) m = fmaxf(m, sh_w[96 + j]);
        float den = 0.f;
        #pragma unroll
        for (int j = 0; j < 16; j++) den += __expf(sh_w[96 + j] - m);
        sh_ga[h] = __fdividef(__expf(sh_w[96 + h] - m), den);
    }
    __syncthreads();

    if (tid < 240) {
        int h = tid / 15, d = tid - h*15;
        g_cw[(s*16 + h)*15 + d] = sh_ga[h] * fmaxf(sh_wR[h*15 + (14 - d)], 0.f);
    }
}

// =====================================================================
// Kernel A2: pack W2 into tf32 (k,k+4) float2 pairs + wc/bias tables
// =====================================================================
__global__ __launch_bounds__(256) void pack_kernel(
    const float* __restrict__ fcT1_W1, const float* __restrict__ fcT2_W1,
    const float* __restrict__ fcT1_W2, const float* __restrict__ fcT1_b2,
    const float* __restrict__ fcT2_W2, const float* __restrict__ fcT2_b2)
{
    int tid = threadIdx.x;
    {
        int k = tid;
        g_wc4[k] = make_float4(fcT1_W1[k*33]     * L2E2,
                               fcT2_W1[k*35]     * L2E2,
                               fcT2_W1[k*35 + 1] * L2E2,
                               fcT2_W1[k*35 + 2] * L2E2);
    }
    if (tid < 48) g_sbias[tid] = (tid < 32) ? fcT1_b2[tid] : fcT2_b2[tid - 32];

    for (int idx = tid; idx < 32*4*48; idx += 256) {
        int j = idx / 192, rem = idx - j*192;
        int c = rem / 48,  o  = rem - c*48;
        int k0 = 8*j + c, k1 = k0 + 4;
        float w0 = (o < 32) ? fcT1_W2[o*256 + k0] : fcT2_W2[(o-32)*256 + k0];
        float w1 = (o < 32) ? fcT1_W2[o*256 + k1] : fcT2_W2[(o-32)*256 + k1];
        g_W2p[(j*4 + c)*49 + o] =
            make_float2(__uint_as_float(cvt_tf32(w0)), __uint_as_float(cvt_tf32(w1)));
    }
}

// =====================================================================
// Kernel B: tensor-core MLP. warp = 16 timesteps x 1 basin.
// =====================================================================
#define SMEM_W2P_F (32*4*49*2)          // 12544 floats
#define SMEM_MLP_BYTES ((SMEM_W2P_F + 256*4 + 8*512 + 48) * 4)   // 70848

__global__ __launch_bounds__(256) void mlp_kernel(const float* __restrict__ x)
{
    extern __shared__ float smem[];
    float2* sW2p  = (float2*)smem;                    // [32*4*49]
    float4* swc   = (float4*)(smem + SMEM_W2P_F);     // [256]
    float*  sbase = smem + SMEM_W2P_F + 256*4;        // [8][512]
    float*  sbias = sbase + 8*512;                    // [48]

    int tid = threadIdx.x;
    int w = tid >> 5, lane = tid & 31;
    int c = lane & 3, r = lane >> 2;

    {
        const uint4* src = (const uint4*)g_W2p;
        uint4* dst = (uint4*)sW2p;
        for (int i = tid; i < SMEM_W2P_F/4; i += 256) dst[i] = src[i];
        swc[tid] = g_wc4[tid];
        if (tid < 48) sbias[tid] = g_sbias[tid];
    }
    int s = blockIdx.y*8 + w;
    {
        float* sb = sbase + w*512;
        const float4* b1s = (const float4*)(g_b1T + s*256);
        const float4* b2s = (const float4*)(g_b2T + s*256);
        for (int i = lane; i < 64; i += 32) {
            ((float4*)sb)[i]        = b1s[i];
            ((float4*)(sb+256))[i]  = b2s[i];
        }
    }
    __syncthreads();

    int t0 = blockIdx.x * 16;
    int tA = t0 + r;              // always < NTT (max 727)
    int tB = tA + 8;              // may overflow on last tile
    int tBl = (tB < NTT) ? tB : (NTT-1);

    const float* xA = x + (size_t)(tA *NSS + s)*6;
    const float* xB = x + (size_t)(tBl*NSS + s)*6;
    float PA = xA[0], EA = xA[1], T1A = xA[2], T2A = xA[3], RA = xA[4], LA = xA[5];
    float PB = xB[0], EB = xB[1], T1B = xB[2], T2B = xB[3], RB = xB[4], LB = xB[5];

    if (c == 0) {
        {
            float dn = T2A - T1A;
            float rr = (T1A + T2A) / (dn == 0.f ? 1.f : dn);
            rr = fminf(fmaxf(rr, -1.f), 1.f);
            if ((T1A >= 0.f) || (T2A <= 0.f)) rr = 0.f;
            float vp = 1.f - acosf(rr) / 3.1415f;
            if (T1A >= 0.f) vp = 1.f;
            if (T2A <= 0.f) vp = 0.f;
            int ts = tA*NSS + s;
            g_Ps[ts] = PA * (1.f - vp);
            g_Pl[ts] = PA * vp;
            g_E[ts]  = EA;
        }
        if (tB < NTT) {
            float dn = T2B - T1B;
            float rr = (T1B + T2B) / (dn == 0.f ? 1.f : dn);
            rr = fminf(fmaxf(rr, -1.f), 1.f);
            if ((T1B >= 0.f) || (T2B <= 0.f)) rr = 0.f;
            float vp = 1.f - acosf(rr) / 3.1415f;
            if (T1B >= 0.f) vp = 1.f;
            if (T2B <= 0.f) vp = 0.f;
            int ts = tB*NSS + s;
            g_Ps[ts] = PB * (1.f - vp);
            g_Pl[ts] = PB * vp;
            g_E[ts]  = EB;
        }
    }

    float dd[6][4];
    #pragma unroll
    for (int g = 0; g < 6; g++)
        #pragma unroll
        for (int i = 0; i < 4; i++) dd[g][i] = 0.f;

    const float* sb1 = sbase + w*512;
    const float* sb2 = sb1 + 256;

    #pragma unroll 2
    for (int j = 0; j < 32; j++) {
        int k0 = j*8 + c;
        float b1k0 = sb1[k0], b1k1 = sb1[k0+4];
        float b2k0 = sb2[k0], b2k1 = sb2[k0+4];
        float4 w0 = swc[k0], w1 = swc[k0+4];

        uint32_t aa1[4], aa2[4];
        aa1[0] = cvt_tf32(tanhe(fmaf(LA, w0.x, b1k0)));
        aa1[1] = cvt_tf32(tanhe(fmaf(LB, w0.x, b1k0)));
        aa1[2] = cvt_tf32(tanhe(fmaf(LA, w1.x, b1k1)));
        aa1[3] = cvt_tf32(tanhe(fmaf(LB, w1.x, b1k1)));
        aa2[0] = cvt_tf32(tanhe(fmaf(RA, w0.y, fmaf(T1A, w0.z, fmaf(T2A, w0.w, b2k0)))));
        aa2[1] = cvt_tf32(tanhe(fmaf(RB, w0.y, fmaf(T1B, w0.z, fmaf(T2B, w0.w, b2k0)))));
        aa2[2] = cvt_tf32(tanhe(fmaf(RA, w1.y, fmaf(T1A, w1.z, fmaf(T2A, w1.w, b2k1)))));
        aa2[3] = cvt_tf32(tanhe(fmaf(RB, w1.y, fmaf(T1B, w1.z, fmaf(T2B, w1.w, b2k1)))));

        const float2* Wrow = sW2p + (j*4 + c)*49;
        #pragma unroll
        for (int g = 0; g < 4; g++) mma8(dd[g], aa1, Wrow[8*g + r]);
        #pragma unroll
        for (int g = 4; g < 6; g++) mma8(dd[g], aa2, Wrow[8*g + r]);
    }

    #pragma unroll
    for (int g = 0; g < 6; g++) {
        int o = 8*g + 2*c;
        float bi0 = sbias[o], bi1 = sbias[o+1];
        float vA0 = dd[g][0] + bi0, vA1 = dd[g][1] + bi1;
        float vB0 = dd[g][2] + bi0, vB1 = dd[g][3] + bi1;
        float2 oA, oB;
        float* arr;
        if (g < 4) {
            oA = make_float2(hsig(vA0), hsig(vA1));
            oB = make_float2(hsig(vB0), hsig(vB1));
            arr = (g < 2) ? g_vi : g_vk;
        } else {
            oA = make_float2(ex2f(vA0*L2E2), ex2f(vA1*L2E2));
            oB = make_float2(ex2f(vB0*L2E2), ex2f(vB1*L2E2));
            arr = g_vm;
        }
        int h = o & 15;
        *(float2*)(arr + (size_t)tA*NSH + s*16 + h) = oA;
        if (tB < NTT)
            *(float2*)(arr + (size_t)tB*NSH + s*16 + h) = oB;
    }
}

// =====================================================================
// Kernel C: sequential reservoir scan; thread = (s,h).
// Software-pipelined: depth-4 circular register buffers, __ldg loads
// (read-only path breaks the store->load alias serialization).
// =====================================================================
#define SCP 4
__global__ __launch_bounds__(128) void scan_kernel()
{
    int g = blockIdx.x * 128 + threadIdx.x;
    if (g >= NSH) return;
    int s = g >> 4;
    float k1 = g_k1[g], k2 = g_k2[g], k23 = g_k23[g], k3 = g_k3[g];
    float gl = g_gl[g], qb = g_qb[g], ge1 = g_ge1[g], ge2 = g_ge2[g];
    float S0 = 0.f, Sv = 0.f, S2 = 0.f, S3 = 0.f;

    float b_vi[SCP], b_vk[SCP], b_vm[SCP], b_Ps[SCP], b_Pl[SCP], b_E[SCP];
    #pragma unroll
    for (int i = 0; i < SCP; i++) {
        size_t tg = (size_t)i*NSH + g;
        int ts = i*NSS + s;
        b_vi[i] = __ldg(g_vi + tg);
        b_vk[i] = __ldg(g_vk + tg);
        b_vm[i] = __ldg(g_vm + tg);
        b_Ps[i] = __ldg(g_Ps + ts);
        b_Pl[i] = __ldg(g_Pl + ts);
        b_E [i] = __ldg(g_E  + ts);
    }

    #pragma unroll 4
    for (int t = 0; t < NTT; t++) {
        int slot = t & (SCP-1);
        float Ps = b_Ps[slot], Pl = b_Pl[slot], E = b_E[slot];
        float vi = b_vi[slot], vk = b_vk[slot], vm = b_vm[slot];

        int tn = t + SCP;
        if (tn < NTT) {
            size_t tg = (size_t)tn*NSH + g;
            int ts = tn*NSS + s;
            b_vi[slot] = __ldg(g_vi + tg);
            b_vk[slot] = __ldg(g_vk + tg);
            b_vm[slot] = __ldg(g_vm + tg);
            b_Ps[slot] = __ldg(g_Ps + ts);
            b_Pl[slot] = __ldg(g_Pl + ts);
            b_E [slot] = __ldg(g_E  + ts);
        }

        float H0  = S0 + Ps;
        float qSm = fminf(H0, vm);
        float Hv  = fmaxf(Sv + Pl*(1.f - vi) - E*ge1, 0.f);
        float qv  = Sv * vk;
        float H2  = fmaxf(S2 + qSm + qv - E*ge2 + Pl*vi, 0.f);
        float x1  = H2 - gl;
        float Q1  = (x1 > 0.f) ? exp2f(k1 * __log2f(x1)) : 0.f;
        float q2  = fminf(H2, gl) * k2;
        float Q2  = q2 * (1.f - k23);
        float H3  = S3 + q2 * k23;
        float Q3  = H3 * k3 + qb;

        S0 = H0 - qSm;
        Sv = Hv - qv;
        S2 = H2 - Q1 - q2;
        S3 = H3 - Q3;
        g_QT[(size_t)t*NSH + g] = Q1 + Q2 + Q3;
    }
}

// =====================================================================
// Kernel D: causal depthwise conv + head-sum, register-blocked 4 t/thread
// =====================================================================
#define CVT 192
#define CVS 788
__global__ __launch_bounds__(CVT) void conv_kernel(float* __restrict__ out)
{
    __shared__ float shQ[16*CVS];
    __shared__ float shc[NHH*NRR];
    int s = blockIdx.x;
    int tid = threadIdx.x;

    for (int i = tid; i < 16*CVS; i += CVT) {
        int j = i >> 4, h = i & 15;
        int t = j - 14;
        shQ[h*CVS + j] = (t >= 0 && t < NTT)
            ? g_QT[(size_t)t*NSH + s*16 + h] : 0.f;
    }
    for (int i = tid; i < 240; i += CVT) shc[i] = g_cw[s*240 + i];
    __syncthreads();

    int tb = tid * 4;
    if (tb < NTT) {
        float acc0 = 0.f, acc1 = 0.f, acc2 = 0.f, acc3 = 0.f;
        #pragma unroll
        for (int h = 0; h < 16; h++) {
            const float4* qw = (const float4*)(shQ + h*CVS + tb);
            float wv[20];
            #pragma unroll
            for (int v = 0; v < 5; v++) {
                float4 q4 = qw[v];
                wv[4*v+0] = q4.x; wv[4*v+1] = q4.y; wv[4*v+2] = q4.z; wv[4*v+3] = q4.w;
            }
            #pragma unroll
            for (int d = 0; d < 15; d++) {
                float cc = shc[h*15 + d];
                acc0 += wv[14 - d] * cc;
                acc1 += wv[15 - d] * cc;
                acc2 += wv[16 - d] * cc;
                acc3 += wv[17 - d] * cc;
            }
        }
        out[(tb+0)*NSS + s] = acc0;
        if (tb+1 < NTT) out[(tb+1)*NSS + s] = acc1;
        if (tb+2 < NTT) out[(tb+2)*NSS + s] = acc2;
        if (tb+3 < NTT) out[(tb+3)*NSS + s] = acc3;
    }
}

// =====================================================================
extern "C" void kernel_launch(void* const* d_in, const int* in_sizes, int n_in,
                              void* d_out, int out_size)
{
    const float* x       = (const float*)d_in[0];
    const float* xc      = (const float*)d_in[1];
    const float* fc_W1   = (const float*)d_in[2];
    const float* fc_b1   = (const float*)d_in[3];
    const float* fc_W2   = (const float*)d_in[4];
    const float* fc_b2   = (const float*)d_in[5];
    const float* fcR_W1  = (const float*)d_in[6];
    const float* fcR_b1  = (const float*)d_in[7];
    const float* fcR_W2  = (const float*)d_in[8];
    const float* fcR_b2  = (const float*)d_in[9];
    const float* fcT1_W1 = (const float*)d_in[10];
    const float* fcT1_b1 = (const float*)d_in[11];
    const float* fcT1_W2 = (const float*)d_in[12];
    const float* fcT1_b2 = (const float*)d_in[13];
    const float* fcT2_W1 = (const float*)d_in[14];
    const float* fcT2_b1 = (const float*)d_in[15];
    const float* fcT2_W2 = (const float*)d_in[16];
    const float* fcT2_b2 = (const float*)d_in[17];

    cudaFuncSetAttribute(mlp_kernel, cudaFuncAttributeMaxDynamicSharedMemorySize,
                         SMEM_MLP_BYTES);

    prep_kernel<<<NSS, 256>>>(xc, fc_W1, fc_b1, fc_W2, fc_b2,
                              fcR_W1, fcR_b1, fcR_W2, fcR_b2,
                              fcT1_W1, fcT1_b1, fcT2_W1, fcT2_b1);

    pack_kernel<<<1, 256>>>(fcT1_W1, fcT2_W1, fcT1_W2, fcT1_b2, fcT2_W2, fcT2_b2);

    dim3 gB((NTT + 15)/16, NSS/8);
    mlp_kernel<<<gB, 256, SMEM_MLP_BYTES>>>(x);

    scan_kernel<<<(NSH + 127)/128, 128>>>();

    conv_kernel<<<NSS, CVT>>>((float*)d_out);
}